// round 13
// baseline (speedup 1.0000x reference)
#include <cuda_runtime.h>
#include <cuda_fp16.h>
#include <cuda_bf16.h>
#include <cstdint>

// Problem constants
#define B_ 4
#define S_ 2048
#define E_ 1024
#define H_ 8
#define O_ 128

#define BSO ((size_t)B_ * S_ * O_)       // 1,048,576
#define NMAT (H_ + 2)                    // 8 Q heads + K + V

// Scratch (allocation-free: __device__ globals)
__device__ float g_QKV[NMAT * BSO];              // z<8: Q head z; 8: K; 9: V
__device__ __nv_bfloat16 g_QKVb[NMAT * BSO];     // bf16 copies (filter pass)
__device__ float g_ctx[(size_t)B_ * S_ * H_ * O_];
// fp16 hi/lo splits of GEMM A operands
__device__ __half g_xh[(size_t)B_ * S_ * E_];
__device__ __half g_xl[(size_t)B_ * S_ * E_];
__device__ __half g_ch[(size_t)B_ * S_ * H_ * O_];
__device__ __half g_cl[(size_t)B_ * S_ * H_ * O_];
// Transposed + fp16-split weights, layout [N][K]: QKV fused, Wo separate
__device__ __half g_wT[2][(size_t)NMAT * O_ * E_];
__device__ __half g_woT[2][(size_t)E_ * H_ * O_];

// ---------------------------------------------------------------------------
__device__ __forceinline__ void cp16(uint32_t dst, const void* src) {
    asm volatile("cp.async.ca.shared.global [%0], [%1], 16;"
                 :: "r"(dst), "l"(src));
}
#define CP_COMMIT() asm volatile("cp.async.commit_group;" ::: "memory")
#define CP_WAIT0()  asm volatile("cp.async.wait_group 0;" ::: "memory")
#define CP_WAIT1()  asm volatile("cp.async.wait_group 1;" ::: "memory")

__device__ __forceinline__ uint32_t smem_u32(const void* p) {
    uint32_t a;
    asm("{ .reg .u64 t; cvta.to.shared.u64 t, %1; cvt.u32.u64 %0, t; }"
        : "=r"(a) : "l"(p));
    return a;
}

// mma.sync m16n8k16 bf16 — D += A*B, fp32 accumulate (baseline sm_80 PTX)
__device__ __forceinline__ void mma_bf16(float* d,
                                         uint32_t a0, uint32_t a1,
                                         uint32_t a2, uint32_t a3,
                                         uint32_t b0, uint32_t b1) {
    asm volatile(
        "mma.sync.aligned.m16n8k16.row.col.f32.bf16.bf16.f32 "
        "{%0,%1,%2,%3}, {%4,%5,%6,%7}, {%8,%9}, {%0,%1,%2,%3};"
        : "+f"(d[0]), "+f"(d[1]), "+f"(d[2]), "+f"(d[3])
        : "r"(a0), "r"(a1), "r"(a2), "r"(a3), "r"(b0), "r"(b1));
}

// mma.sync m16n8k16 fp16 — D += A*B, fp32 accumulate (baseline sm_80 PTX)
__device__ __forceinline__ void mma_f16(float* d, const uint32_t a[4],
                                        uint32_t b0, uint32_t b1) {
    asm volatile(
        "mma.sync.aligned.m16n8k16.row.col.f32.f16.f16.f32 "
        "{%0,%1,%2,%3}, {%4,%5,%6,%7}, {%8,%9}, {%0,%1,%2,%3};"
        : "+f"(d[0]), "+f"(d[1]), "+f"(d[2]), "+f"(d[3])
        : "r"(a[0]), "r"(a[1]), "r"(a[2]), "r"(a[3]), "r"(b0), "r"(b1));
}

// ---------------------------------------------------------------------------
// fp32 -> fp16 hi/lo split, bulk (n % 4 == 0)
// ---------------------------------------------------------------------------
__global__ void split_h(const float* __restrict__ in,
                        __half* __restrict__ oh, __half* __restrict__ ol,
                        int n)
{
    int i = (blockIdx.x * blockDim.x + threadIdx.x) * 4;
    if (i < n) {
        float4 v = *(const float4*)(in + i);
        __half2 h0 = __floats2half2_rn(v.x, v.y);
        __half2 h1 = __floats2half2_rn(v.z, v.w);
        float2 f0 = __half22float2(h0);
        float2 f1 = __half22float2(h1);
        __half2 l0 = __floats2half2_rn(v.x - f0.x, v.y - f0.y);
        __half2 l1 = __floats2half2_rn(v.z - f1.x, v.w - f1.y);
        *(__half2*)(oh + i)     = h0;
        *(__half2*)(oh + i + 2) = h1;
        *(__half2*)(ol + i)     = l0;
        *(__half2*)(ol + i + 2) = l1;
    }
}

// ---------------------------------------------------------------------------
// Weight transpose + fp16 hi/lo split: in[K][N] (+z*sIn) -> hi/lo [N][K]
// grid (N/32, K/32, Z), block (32, 8)
// ---------------------------------------------------------------------------
__global__ void transpose_split_h(const float* __restrict__ in,
                                  __half* __restrict__ oh,
                                  __half* __restrict__ ol,
                                  int K, int N, long long sIn, long long sOut)
{
    __shared__ float t[32][33];
    const float* ip = in + (long long)blockIdx.z * sIn;
    __half* ph = oh + (long long)blockIdx.z * sOut;
    __half* pl = ol + (long long)blockIdx.z * sOut;
    const int n0 = blockIdx.x * 32, k0 = blockIdx.y * 32;
    const int tx = threadIdx.x, ty = threadIdx.y;
#pragma unroll
    for (int p = 0; p < 4; p++)
        t[ty + 8 * p][tx] = ip[(long long)(k0 + ty + 8 * p) * N + n0 + tx];
    __syncthreads();
#pragma unroll
    for (int p = 0; p < 4; p++) {
        float v = t[tx][ty + 8 * p];
        __half h = __float2half_rn(v);
        __half l = __float2half_rn(v - __half2float(h));
        long long o = (long long)(n0 + ty + 8 * p) * K + k0 + tx;
        ph[o] = h;
        pl[o] = l;
    }
}

// ---------------------------------------------------------------------------
// fp16x2 split GEMM v2 (all-fp16 inputs, 3-stage cp.async pipeline):
// C[M,Ntot] = Ahl[M,K] @ Bt[N,K]^T   (3 products: hh + hl + lh, ~22-bit)
// Block 128x128x32, 256 threads (8 warps: 4m x 2n, warp tile 32x64).
// grid (Ntot/128, M/128, Z); B += z*sBz, C += z*sCz. Optional bf16 out Cb.
// ---------------------------------------------------------------------------
#define HS 20                        // u32 stride per smem row (bank-clean)
#define STA_H 0
#define STA_L 2560
#define STB_H 5120
#define STB_L 7680
#define STAGE 10240                  // u32 per stage
#define HG_SMEM (3 * STAGE * 4)      // 122880 bytes

__global__ __launch_bounds__(256) void hgemm3(
    const __half* __restrict__ Ah, const __half* __restrict__ Al,
    const __half* __restrict__ Bth, const __half* __restrict__ Btl,
    float* __restrict__ C, __nv_bfloat16* __restrict__ Cb,
    int K, int Ntot, long long sBz, long long sCz)
{
    extern __shared__ __align__(16) uint32_t su[];
    const int tid = threadIdx.x, w = tid >> 5, lane = tid & 31;
    const int g = lane >> 2, tq = lane & 3;
    const int wm = w & 3, wn = w >> 2;
    const int m0 = blockIdx.y * 128, n0 = blockIdx.x * 128;
    const __half* Bh_g = Bth + (long long)blockIdx.z * sBz;
    const __half* Bl_g = Btl + (long long)blockIdx.z * sBz;
    float* Cp = C + (long long)blockIdx.z * sCz;
    __nv_bfloat16* Cbp = Cb ? Cb + (long long)blockIdx.z * sCz
                            : (__nv_bfloat16*)0;
    const uint32_t sb = smem_u32(su);
    const int NK = K >> 5;

    // Fill mapping: tid<128 handles hi arrays row tid, else lo arrays row-128
    const int row = tid & 127;
    const bool hiside = tid < 128;
    const __half* aB = hiside ? Ah : Al;
    const __half* bB = hiside ? Bh_g : Bl_g;
    const uint32_t soA = hiside ? STA_H : STA_L;
    const uint32_t soB = hiside ? STB_H : STB_L;

    auto fill = [&](int kt, int st) {
        const __half* sa = aB + (long long)(m0 + row) * K + (kt << 5);
        const __half* sbp = bB + (long long)(n0 + row) * K + (kt << 5);
        uint32_t da = sb + (st * STAGE + soA + row * HS) * 4;
        uint32_t db = sb + (st * STAGE + soB + row * HS) * 4;
        cp16(da, sa);           cp16(da + 16, sa + 8);
        cp16(da + 32, sa + 16); cp16(da + 48, sa + 24);
        cp16(db, sbp);          cp16(db + 16, sbp + 8);
        cp16(db + 32, sbp + 16); cp16(db + 48, sbp + 24);
    };

    float acc[2][8][4];
#pragma unroll
    for (int mi = 0; mi < 2; mi++)
#pragma unroll
        for (int nj = 0; nj < 8; nj++)
#pragma unroll
            for (int q = 0; q < 4; q++) acc[mi][nj][q] = 0.f;

    // Prologue: stages 0 and 1 in flight
    fill(0, 0);
    CP_COMMIT();
    if (NK > 1) { fill(1, 1); CP_COMMIT(); }

    for (int kt = 0; kt < NK; kt++) {
        if (kt + 1 < NK) { CP_WAIT1(); } else { CP_WAIT0(); }
        __syncthreads();                 // stage kt ready; stage (kt+2)%3 free
        if (kt + 2 < NK) {
            fill(kt + 2, (kt + 2) % 3);
            CP_COMMIT();
        }

        const uint32_t* bufp = su + (kt % 3) * STAGE;
#pragma unroll
        for (int ks = 0; ks < 2; ks++) {
            uint32_t ah[2][4], al[2][4];
#pragma unroll
            for (int mi = 0; mi < 2; mi++) {
                int r = (wm * 32 + mi * 16 + g) * HS + ks * 8 + tq;
                ah[mi][0] = bufp[STA_H + r];
                ah[mi][1] = bufp[STA_H + r + 8 * HS];
                ah[mi][2] = bufp[STA_H + r + 4];
                ah[mi][3] = bufp[STA_H + r + 8 * HS + 4];
                al[mi][0] = bufp[STA_L + r];
                al[mi][1] = bufp[STA_L + r + 8 * HS];
                al[mi][2] = bufp[STA_L + r + 4];
                al[mi][3] = bufp[STA_L + r + 8 * HS + 4];
            }
#pragma unroll
            for (int nj = 0; nj < 8; nj++) {
                int nb = (wn * 64 + nj * 8 + g) * HS + ks * 8 + tq;
                uint32_t bh0 = bufp[STB_H + nb], bh1 = bufp[STB_H + nb + 4];
                uint32_t bl0 = bufp[STB_L + nb], bl1 = bufp[STB_L + nb + 4];
#pragma unroll
                for (int mi = 0; mi < 2; mi++) {
                    mma_f16(acc[mi][nj], ah[mi], bh0, bh1);  // hi*hi
                    mma_f16(acc[mi][nj], ah[mi], bl0, bl1);  // hi*lo
                    mma_f16(acc[mi][nj], al[mi], bh0, bh1);  // lo*hi
                }
            }
        }
    }

    // Epilogue: fp32 C (+ optional bf16 Cb)
#pragma unroll
    for (int mi = 0; mi < 2; mi++) {
#pragma unroll
        for (int nj = 0; nj < 8; nj++) {
            int r0 = m0 + wm * 32 + mi * 16 + g;
            int c0 = n0 + wn * 64 + nj * 8 + 2 * tq;
            float2 v0 = make_float2(acc[mi][nj][0], acc[mi][nj][1]);
            float2 v1 = make_float2(acc[mi][nj][2], acc[mi][nj][3]);
            *(float2*)&Cp[(long long)r0 * Ntot + c0] = v0;
            *(float2*)&Cp[(long long)(r0 + 8) * Ntot + c0] = v1;
            if (Cbp) {
                *(__nv_bfloat162*)&Cbp[(long long)r0 * Ntot + c0] =
                    __floats2bfloat162_rn(v0.x, v0.y);
                *(__nv_bfloat162*)&Cbp[(long long)(r0 + 8) * Ntot + c0] =
                    __floats2bfloat162_rn(v1.x, v1.y);
            }
        }
    }
}

// ---------------------------------------------------------------------------
// Attention (unchanged logic): bf16 HMMA filter + exact fp32 re-check.
// grid (S/64, H, B), 512 threads.
// ---------------------------------------------------------------------------
#define CAP 32
#define THRESH  40.0f
#define FMARGIN 170.0f
#define ATTN_SMEM ((3 * 64 * 68 + 64 * 68 + 64 + 64 * CAP + 64 + 64 * CAP) * 4)

__global__ __launch_bounds__(512) void attn_kernel()
{
    extern __shared__ __align__(16) uint32_t smu[];
    uint32_t* Qs   = smu;                       // 64 x 68 u32 (bf16 pairs)
    uint32_t* Ks   = Qs + 64 * 68;              // 2 x 64 x 68 u32
    float*    Sc   = (float*)(Ks + 2 * 64 * 68);// 64 x 68 approx scores
    float*    maxv = Sc + 64 * 68;              // 64
    float*    candS= maxv + 64;                 // 64 x CAP
    int*      cnt  = (int*)(candS + 64 * CAP);  // 64
    int*      candK= cnt + 64;                  // 64 x CAP

    const int t  = threadIdx.x;
    const int q0 = blockIdx.x * 64;
    const int h  = blockIdx.y;
    const int b  = blockIdx.z;

    const int r_ = t >> 3;
    const int c8 = (t & 7) << 3;

    {
        const uint4* Qgb = (const uint4*)(g_QKVb +
            ((long long)h * BSO + ((long long)b * S_ + q0) * O_));
        uint4 v0 = Qgb[r_ * 16 + (c8 >> 2)];
        uint4 v1 = Qgb[r_ * 16 + (c8 >> 2) + 1];
        *(uint4*)&Qs[r_ * 68 + c8]     = v0;
        *(uint4*)&Qs[r_ * 68 + c8 + 4] = v1;
    }
    if (t < 64) { maxv[t] = -1e30f; cnt[t] = 0; }

    const float* Kg = g_QKV + 8 * BSO + (long long)b * S_ * O_;
    const float* Vg = g_QKV + 9 * BSO + (long long)b * S_ * O_;
    const __nv_bfloat16* Kgb = g_QKVb + 8 * BSO + (long long)b * S_ * O_;
    const float scale = 0.08838834764831845f;

    const uint32_t ksb = smem_u32(Ks);
    auto fillK = [&](int kt, int buf) {
        uint32_t dst = ksb + (buf * 64 * 68 + r_ * 68 + c8) * 4;
        const __nv_bfloat16* src = Kgb + ((long long)(kt * 64 + r_) * O_) + c8 * 2;
        cp16(dst, src);
        cp16(dst + 16, src + 8);
    };

    const int w = t >> 5, lane = t & 31;
    const int g = lane >> 2, tq = lane & 3;
    const int qb = (w >> 2) << 4, kb = (w & 3) << 4;

    fillK(0, 0);
    CP_COMMIT();

    for (int kt = 0; kt < S_ / 64; kt++) {
        const int cur = kt & 1;
        CP_WAIT0();
        __syncthreads();
        if (kt + 1 < S_ / 64) {
            fillK(kt + 1, cur ^ 1);
            CP_COMMIT();
        }

        {
            const uint32_t* Kb32 = Ks + cur * 64 * 68;
            float d0[4] = {0.f, 0.f, 0.f, 0.f};
            float d1[4] = {0.f, 0.f, 0.f, 0.f};
#pragma unroll
            for (int kc = 0; kc < 8; kc++) {
                const int co = kc * 8 + tq;
                uint32_t a0 = Qs[(qb + g) * 68 + co];
                uint32_t a1 = Qs[(qb + g + 8) * 68 + co];
                uint32_t a2 = Qs[(qb + g) * 68 + co + 4];
                uint32_t a3 = Qs[(qb + g + 8) * 68 + co + 4];
                uint32_t b0 = Kb32[(kb + g) * 68 + co];
                uint32_t b1 = Kb32[(kb + g) * 68 + co + 4];
                uint32_t b2 = Kb32[(kb + 8 + g) * 68 + co];
                uint32_t b3 = Kb32[(kb + 8 + g) * 68 + co + 4];
                mma_bf16(d0, a0, a1, a2, a3, b0, b1);
                mma_bf16(d1, a0, a1, a2, a3, b2, b3);
            }
            *(float2*)&Sc[(qb + g) * 68 + kb + 2 * tq] =
                make_float2(d0[0] * scale, d0[1] * scale);
            *(float2*)&Sc[(qb + g + 8) * 68 + kb + 2 * tq] =
                make_float2(d0[2] * scale, d0[3] * scale);
            *(float2*)&Sc[(qb + g) * 68 + kb + 8 + 2 * tq] =
                make_float2(d1[0] * scale, d1[1] * scale);
            *(float2*)&Sc[(qb + g + 8) * 68 + kb + 8 + 2 * tq] =
                make_float2(d1[2] * scale, d1[3] * scale);
        }
        __syncthreads();

        if (t < 64) {
            float mx = maxv[t];
            int c = cnt[t];
            float thr = mx - FMARGIN;
            const float4* sr = (const float4*)&Sc[t * 68];
            float* cS = &candS[t * CAP];
            int*   cK = &candK[t * CAP];
#pragma unroll 4
            for (int j4 = 0; j4 < 16; j4++) {
                float4 v = sr[j4];
                float m4 = fmaxf(fmaxf(v.x, v.y), fmaxf(v.z, v.w));
                if (m4 > thr) {
                    float ss[4] = {v.x, v.y, v.z, v.w};
#pragma unroll
                    for (int u = 0; u < 4; u++) {
                        float s = ss[u];
                        if (s > thr) {
                            if (s > mx) { mx = s; thr = mx - FMARGIN; }
                            if (c == CAP) {
                                int wj = 0;
                                for (int i = 0; i < CAP; i++)
                                    if (cS[i] > thr) {
                                        cS[wj] = cS[i]; cK[wj] = cK[i]; wj++;
                                    }
                                c = wj;
                            }
                            if (c < CAP) {
                                cS[c] = s; cK[c] = kt * 64 + j4 * 4 + u; c++;
                            } else {
                                int am = 0; float mv = cS[0];
                                for (int i = 1; i < CAP; i++)
                                    if (cS[i] < mv) { mv = cS[i]; am = i; }
                                if (s > mv) { cS[am] = s; cK[am] = kt * 64 + j4 * 4 + u; }
                            }
                        }
                    }
                }
            }
            maxv[t] = mx; cnt[t] = c;
        }
        __syncthreads();
    }

    // Final: exact fp32 re-check + softmax + V gather
    const float* Qg = g_QKV + (long long)h * BSO + ((long long)b * S_ + q0) * O_;
#pragma unroll
    for (int i = 0; i < 4; i++) {
        const int r = 4 * w + i;
        const int c = cnt[r];
        float* cS = &candS[r * CAP];
        int*   cK = &candK[r * CAP];
        const float4 qv = ((const float4*)(Qg + (long long)r * O_))[lane];

        for (int idx = 0; idx < c; idx++) {
            const float4 kv = ((const float4*)(Kg + (long long)cK[idx] * O_))[lane];
            float d = qv.x * kv.x + qv.y * kv.y + qv.z * kv.z + qv.w * kv.w;
#pragma unroll
            for (int o = 16; o; o >>= 1) d += __shfl_xor_sync(~0u, d, o);
            if (lane == 0) cS[idx] = d * scale;
        }
        __syncwarp();

        float mx = -1e30f;
        for (int idx = 0; idx < c; idx++) mx = fmaxf(mx, cS[idx]);

        float4 a = make_float4(0.f, 0.f, 0.f, 0.f);
        float l = 0.f;
        for (int idx = 0; idx < c; idx++) {
            float s = cS[idx];
            if (s < mx - THRESH) continue;
            float p = __expf(s - mx);
            const float4 v = ((const float4*)(Vg + (long long)cK[idx] * O_))[lane];
            l += p;
            a.x += p * v.x; a.y += p * v.y; a.z += p * v.z; a.w += p * v.w;
        }
        const float inv = 1.0f / l;
        float* cp = &g_ctx[(((long long)b * S_ + q0 + r) * H_ + h) * O_ + lane * 4];
        *(float4*)cp = make_float4(a.x * inv, a.y * inv, a.z * inv, a.w * inv);
    }
}

// ---------------------------------------------------------------------------
extern "C" void kernel_launch(void* const* d_in, const int* in_sizes, int n_in,
                              void* d_out, int out_size)
{
    const float* x  = (const float*)d_in[0];
    const float* Wq = (const float*)d_in[1];
    const float* Wk = (const float*)d_in[2];
    const float* Wv = (const float*)d_in[3];
    const float* Wo = (const float*)d_in[4];
    float* out = (float*)d_out;

    float *QKVp, *Cp;
    __nv_bfloat16 *QKVb;
    __half *xh, *xl, *ch, *cl, *wT, *wo;
    cudaGetSymbolAddress((void**)&QKVp, g_QKV);
    cudaGetSymbolAddress((void**)&QKVb, g_QKVb);
    cudaGetSymbolAddress((void**)&Cp, g_ctx);
    cudaGetSymbolAddress((void**)&xh, g_xh);
    cudaGetSymbolAddress((void**)&xl, g_xl);
    cudaGetSymbolAddress((void**)&ch, g_ch);
    cudaGetSymbolAddress((void**)&cl, g_cl);
    cudaGetSymbolAddress((void**)&wT, g_wT);
    cudaGetSymbolAddress((void**)&wo, g_woT);

    const size_t wH  = (size_t)NMAT * O_ * E_;      // hi/lo half offset (QKV)
    const size_t woH = (size_t)E_ * H_ * O_;
    const size_t OE  = (size_t)O_ * E_;

    cudaFuncSetAttribute(hgemm3,
                         cudaFuncAttributeMaxDynamicSharedMemorySize, HG_SMEM);
    cudaFuncSetAttribute(attn_kernel,
                         cudaFuncAttributeMaxDynamicSharedMemorySize, ATTN_SMEM);

    const int M = B_ * S_;  // 8192
    const int nX = M * E_;  // 8.4M

    // A-operand split: x -> fp16 hi/lo (once, reused by all 10 projections)
    split_h<<<nX / 4 / 256, 256>>>(x, xh, xl, nX);

    // Weight transpose + fp16 split into fused layout [z][N][K]
    transpose_split_h<<<dim3(O_ / 32, E_ / 32, H_), dim3(32, 8)>>>(
        Wq, wT, wT + wH, E_, O_, (long long)E_ * O_, (long long)OE);
    transpose_split_h<<<dim3(O_ / 32, E_ / 32, 1), dim3(32, 8)>>>(
        Wk, wT + 8 * OE, wT + wH + 8 * OE, E_, O_, 0, 0);
    transpose_split_h<<<dim3(O_ / 32, E_ / 32, 1), dim3(32, 8)>>>(
        Wv, wT + 9 * OE, wT + wH + 9 * OE, E_, O_, 0, 0);
    transpose_split_h<<<dim3(E_ / 32, (H_ * O_) / 32, 1), dim3(32, 8)>>>(
        Wo, wo, wo + woH, H_ * O_, E_, 0, 0);

    // Fused Q/K/V projections: z in [0,10), shared A=x, bf16 epilogue copies
    hgemm3<<<dim3(1, M / 128, NMAT), 256, HG_SMEM>>>(
        xh, xl, wT, wT + wH, QKVp, QKVb, E_, O_,
        (long long)OE, (long long)BSO);

    // Attention (bf16 HMMA filter + exact re-check + gather)
    attn_kernel<<<dim3(S_ / 64, H_, B_), 512, ATTN_SMEM>>>();

    // ctx split + output projection: (B*S, H*O) @ (H*O, E) -> d_out
    const int nC = M * H_ * O_;
    split_h<<<nC / 4 / 256, 256>>>(Cp, ch, cl, nC);
    hgemm3<<<dim3(E_ / 128, M / 128, 1), 256, HG_SMEM>>>(
        ch, cl, wo, wo + woH, out, (__nv_bfloat16*)0, H_ * O_, E_, 0, 0);
}

// round 14
// speedup vs baseline: 1.0894x; 1.0894x over previous
#include <cuda_runtime.h>
#include <cuda_fp16.h>
#include <cuda_bf16.h>
#include <cstdint>

// Problem constants
#define B_ 4
#define S_ 2048
#define E_ 1024
#define H_ 8
#define O_ 128

#define BSO ((size_t)B_ * S_ * O_)       // 1,048,576
#define NMAT (H_ + 2)                    // 8 Q heads + K + V

// Scratch (allocation-free: __device__ globals)
__device__ float g_QKV[NMAT * BSO];              // z<8: Q head z; 8: K; 9: V
__device__ __nv_bfloat16 g_QKVb[NMAT * BSO];     // bf16 copies (filter pass)
__device__ float g_ctx[(size_t)B_ * S_ * H_ * O_];
// fp16 hi/lo splits of GEMM A operands
__device__ __half g_xh[(size_t)B_ * S_ * E_];
__device__ __half g_xl[(size_t)B_ * S_ * E_];
__device__ __half g_ch[(size_t)B_ * S_ * H_ * O_];
__device__ __half g_cl[(size_t)B_ * S_ * H_ * O_];
// Transposed + fp16-split weights, layout [N][K]: QKV fused, Wo separate
__device__ __half g_wT[2][(size_t)NMAT * O_ * E_];
__device__ __half g_woT[2][(size_t)E_ * H_ * O_];

// ---------------------------------------------------------------------------
__device__ __forceinline__ void cp16(uint32_t dst, const void* src) {
    asm volatile("cp.async.ca.shared.global [%0], [%1], 16;"
                 :: "r"(dst), "l"(src));
}
#define CP_COMMIT() asm volatile("cp.async.commit_group;" ::: "memory")
#define CP_WAIT0()  asm volatile("cp.async.wait_group 0;" ::: "memory")
#define CP_WAIT1()  asm volatile("cp.async.wait_group 1;" ::: "memory")

__device__ __forceinline__ uint32_t smem_u32(const void* p) {
    uint32_t a;
    asm("{ .reg .u64 t; cvta.to.shared.u64 t, %1; cvt.u32.u64 %0, t; }"
        : "=r"(a) : "l"(p));
    return a;
}

// ldmatrix 4x(8x8) b16 fragments — baseline sm_75 PTX
__device__ __forceinline__ void ldm4(uint32_t* r, uint32_t addr) {
    asm volatile(
        "ldmatrix.sync.aligned.m8n8.x4.shared.b16 {%0,%1,%2,%3}, [%4];"
        : "=r"(r[0]), "=r"(r[1]), "=r"(r[2]), "=r"(r[3]) : "r"(addr));
}

// mma.sync m16n8k16 bf16 — D += A*B, fp32 accumulate (baseline sm_80 PTX)
__device__ __forceinline__ void mma_bf16(float* d,
                                         uint32_t a0, uint32_t a1,
                                         uint32_t a2, uint32_t a3,
                                         uint32_t b0, uint32_t b1) {
    asm volatile(
        "mma.sync.aligned.m16n8k16.row.col.f32.bf16.bf16.f32 "
        "{%0,%1,%2,%3}, {%4,%5,%6,%7}, {%8,%9}, {%0,%1,%2,%3};"
        : "+f"(d[0]), "+f"(d[1]), "+f"(d[2]), "+f"(d[3])
        : "r"(a0), "r"(a1), "r"(a2), "r"(a3), "r"(b0), "r"(b1));
}

// mma.sync m16n8k16 fp16 — D += A*B, fp32 accumulate (baseline sm_80 PTX)
__device__ __forceinline__ void mma_f16(float* d, const uint32_t a[4],
                                        uint32_t b0, uint32_t b1) {
    asm volatile(
        "mma.sync.aligned.m16n8k16.row.col.f32.f16.f16.f32 "
        "{%0,%1,%2,%3}, {%4,%5,%6,%7}, {%8,%9}, {%0,%1,%2,%3};"
        : "+f"(d[0]), "+f"(d[1]), "+f"(d[2]), "+f"(d[3])
        : "r"(a[0]), "r"(a[1]), "r"(a[2]), "r"(a[3]), "r"(b0), "r"(b1));
}

// ---------------------------------------------------------------------------
// fp32 -> fp16 hi/lo split, bulk (n % 4 == 0)
// ---------------------------------------------------------------------------
__global__ void split_h(const float* __restrict__ in,
                        __half* __restrict__ oh, __half* __restrict__ ol,
                        int n)
{
    int i = (blockIdx.x * blockDim.x + threadIdx.x) * 4;
    if (i < n) {
        float4 v = *(const float4*)(in + i);
        __half2 h0 = __floats2half2_rn(v.x, v.y);
        __half2 h1 = __floats2half2_rn(v.z, v.w);
        float2 f0 = __half22float2(h0);
        float2 f1 = __half22float2(h1);
        __half2 l0 = __floats2half2_rn(v.x - f0.x, v.y - f0.y);
        __half2 l1 = __floats2half2_rn(v.z - f1.x, v.w - f1.y);
        *(__half2*)(oh + i)     = h0;
        *(__half2*)(oh + i + 2) = h1;
        *(__half2*)(ol + i)     = l0;
        *(__half2*)(ol + i + 2) = l1;
    }
}

// ---------------------------------------------------------------------------
// Weight transpose + fp16 hi/lo split: in[K][N] (+z*sIn) -> hi/lo [N][K]
// grid (N/32, K/32, Z), block (32, 8)
// ---------------------------------------------------------------------------
__global__ void transpose_split_h(const float* __restrict__ in,
                                  __half* __restrict__ oh,
                                  __half* __restrict__ ol,
                                  int K, int N, long long sIn, long long sOut)
{
    __shared__ float t[32][33];
    const float* ip = in + (long long)blockIdx.z * sIn;
    __half* ph = oh + (long long)blockIdx.z * sOut;
    __half* pl = ol + (long long)blockIdx.z * sOut;
    const int n0 = blockIdx.x * 32, k0 = blockIdx.y * 32;
    const int tx = threadIdx.x, ty = threadIdx.y;
#pragma unroll
    for (int p = 0; p < 4; p++)
        t[ty + 8 * p][tx] = ip[(long long)(k0 + ty + 8 * p) * N + n0 + tx];
    __syncthreads();
#pragma unroll
    for (int p = 0; p < 4; p++) {
        float v = t[tx][ty + 8 * p];
        __half h = __float2half_rn(v);
        __half l = __float2half_rn(v - __half2float(h));
        long long o = (long long)(n0 + ty + 8 * p) * K + k0 + tx;
        ph[o] = h;
        pl[o] = l;
    }
}

// ---------------------------------------------------------------------------
// fp16x2 split GEMM v3: ldmatrix fragments + 256x128x32 tile, 256 threads
// (8 warps: 4m x 2n, warp tile 64x64), 3-stage cp.async pipeline.
// C[M,Ntot] = Ahl[M,K] @ Bt[N,K]^T  (hh + hl + lh, ~22-bit exact)
// zsplit=1: output cols are [z][128] slices of stride BSO (QKV fused layout),
//           optional bf16 copy Cb. zsplit=0: plain row-major C[M][Ntot].
// ---------------------------------------------------------------------------
#define HS 20                        // u32 stride per smem row (bank-clean)
#define STA_H 0
#define STA_L 5120
#define STB_H 10240
#define STB_L 12800
#define STAGE 15360                  // u32 per stage (61440 B)
#define NSTG 3
#define HG_SMEM (NSTG * STAGE * 4)   // 184320 bytes

__global__ __launch_bounds__(256, 1) void hgemm3(
    const __half* __restrict__ Ah, const __half* __restrict__ Al,
    const __half* __restrict__ Bth, const __half* __restrict__ Btl,
    float* __restrict__ C, __nv_bfloat16* __restrict__ Cb,
    int K, int Ntot, int zsplit)
{
    extern __shared__ __align__(16) uint32_t su[];
    const int tid = threadIdx.x, w = tid >> 5, lane = tid & 31;
    const int g = lane >> 2, tq = lane & 3;
    const int wm = w & 3, wn = w >> 2;
    const int m0 = blockIdx.y * 256, n0 = blockIdx.x * 128;
    const uint32_t sb = smem_u32(su);
    const int NK = K >> 5;

    // Fill precompute: 768 virtual rows (Ah 256, Al 256, Bh 128, Bl 128),
    // thread handles rows tid, tid+256, tid+512; 4 cp16 per row.
    const __half* srcp[3];
    uint32_t dsto[3];
#pragma unroll
    for (int j = 0; j < 3; j++) {
        int vr = tid + (j << 8);
        if (vr < 256)      { srcp[j] = Ah  + (size_t)(m0 + vr) * K;
                             dsto[j] = STA_H + vr * HS; }
        else if (vr < 512) { srcp[j] = Al  + (size_t)(m0 + vr - 256) * K;
                             dsto[j] = STA_L + (vr - 256) * HS; }
        else if (vr < 640) { srcp[j] = Bth + (size_t)(n0 + vr - 512) * K;
                             dsto[j] = STB_H + (vr - 512) * HS; }
        else               { srcp[j] = Btl + (size_t)(n0 + vr - 640) * K;
                             dsto[j] = STB_L + (vr - 640) * HS; }
    }
    auto fill = [&](int kt, int st) {
#pragma unroll
        for (int j = 0; j < 3; j++) {
            const __half* sp = srcp[j] + (kt << 5);
            uint32_t d = sb + (st * STAGE + dsto[j]) * 4;
            cp16(d, sp);           cp16(d + 16, sp + 8);
            cp16(d + 32, sp + 16); cp16(d + 48, sp + 24);
        }
    };

    // ldmatrix lane-relative offsets (u32 units), matching mma fragment order
    const uint32_t a_ro = (uint32_t)((wm * 64 + (lane & 15)) * HS +
                                     ((lane >> 4) << 2));
    const uint32_t b_ro = (uint32_t)((wn * 64 + (lane & 7) +
                                      ((lane >> 4) << 3)) * HS +
                                     (((lane >> 3) & 1) << 2));

    float acc[4][8][4];
#pragma unroll
    for (int mi = 0; mi < 4; mi++)
#pragma unroll
        for (int nj = 0; nj < 8; nj++)
#pragma unroll
            for (int q = 0; q < 4; q++) acc[mi][nj][q] = 0.f;

    // Prologue: stages 0, 1 in flight
    fill(0, 0);
    CP_COMMIT();
    if (NK > 1) { fill(1, 1); CP_COMMIT(); }

    for (int kt = 0; kt < NK; kt++) {
        if (kt + 1 < NK) { CP_WAIT1(); } else { CP_WAIT0(); }
        __syncthreads();                 // stage kt ready; stage (kt+2)%3 free
        if (kt + 2 < NK) {
            fill(kt + 2, (kt + 2) % 3);
            CP_COMMIT();
        }

        const uint32_t stb = sb + ((kt % 3) * STAGE) * 4;
#pragma unroll
        for (int ks = 0; ks < 2; ks++) {
            uint32_t AH[4][4], AL[4][4];
#pragma unroll
            for (int mi = 0; mi < 4; mi++) {
                uint32_t ao = stb + (STA_H + a_ro + mi * 16 * HS + ks * 8) * 4;
                ldm4(AH[mi], ao);
                ldm4(AL[mi], ao + (STA_L - STA_H) * 4);
            }
#pragma unroll
            for (int njp = 0; njp < 4; njp++) {
                uint32_t BH[4], BL[4];
                uint32_t bo = stb + (STB_H + b_ro + njp * 16 * HS + ks * 8) * 4;
                ldm4(BH, bo);
                ldm4(BL, bo + (STB_L - STB_H) * 4);
#pragma unroll
                for (int mi = 0; mi < 4; mi++) {
                    mma_f16(acc[mi][2 * njp],     AH[mi], BH[0], BH[1]);
                    mma_f16(acc[mi][2 * njp],     AH[mi], BL[0], BL[1]);
                    mma_f16(acc[mi][2 * njp],     AL[mi], BH[0], BH[1]);
                    mma_f16(acc[mi][2 * njp + 1], AH[mi], BH[2], BH[3]);
                    mma_f16(acc[mi][2 * njp + 1], AH[mi], BL[2], BL[3]);
                    mma_f16(acc[mi][2 * njp + 1], AL[mi], BH[2], BH[3]);
                }
            }
        }
    }

    // Epilogue
#pragma unroll
    for (int mi = 0; mi < 4; mi++) {
#pragma unroll
        for (int nj = 0; nj < 8; nj++) {
            int r0 = m0 + wm * 64 + mi * 16 + g;
            int cg = n0 + wn * 64 + nj * 8 + 2 * tq;
            float* base;
            long long rs;
            __nv_bfloat16* bb = 0;
            if (zsplit) {
                int z = cg >> 7, o = cg & 127;
                base = C + (size_t)z * BSO + (size_t)r0 * 128 + o;
                rs = 128;
                if (Cb) bb = Cb + (size_t)z * BSO + (size_t)r0 * 128 + o;
            } else {
                base = C + (size_t)r0 * Ntot + cg;
                rs = Ntot;
            }
            float2 v0 = make_float2(acc[mi][nj][0], acc[mi][nj][1]);
            float2 v1 = make_float2(acc[mi][nj][2], acc[mi][nj][3]);
            *(float2*)base = v0;
            *(float2*)(base + 8 * rs) = v1;
            if (bb) {
                *(__nv_bfloat162*)bb = __floats2bfloat162_rn(v0.x, v0.y);
                *(__nv_bfloat162*)(bb + 8 * rs) =
                    __floats2bfloat162_rn(v1.x, v1.y);
            }
        }
    }
}

// ---------------------------------------------------------------------------
// Attention (unchanged, passing): bf16 HMMA filter + exact fp32 re-check.
// grid (S/64, H, B), 512 threads.
// ---------------------------------------------------------------------------
#define CAP 32
#define THRESH  40.0f
#define FMARGIN 170.0f
#define ATTN_SMEM ((3 * 64 * 68 + 64 * 68 + 64 + 64 * CAP + 64 + 64 * CAP) * 4)

__global__ __launch_bounds__(512) void attn_kernel()
{
    extern __shared__ __align__(16) uint32_t smu[];
    uint32_t* Qs   = smu;                       // 64 x 68 u32 (bf16 pairs)
    uint32_t* Ks   = Qs + 64 * 68;              // 2 x 64 x 68 u32
    float*    Sc   = (float*)(Ks + 2 * 64 * 68);// 64 x 68 approx scores
    float*    maxv = Sc + 64 * 68;              // 64
    float*    candS= maxv + 64;                 // 64 x CAP
    int*      cnt  = (int*)(candS + 64 * CAP);  // 64
    int*      candK= cnt + 64;                  // 64 x CAP

    const int t  = threadIdx.x;
    const int q0 = blockIdx.x * 64;
    const int h  = blockIdx.y;
    const int b  = blockIdx.z;

    const int r_ = t >> 3;
    const int c8 = (t & 7) << 3;

    {
        const uint4* Qgb = (const uint4*)(g_QKVb +
            ((long long)h * BSO + ((long long)b * S_ + q0) * O_));
        uint4 v0 = Qgb[r_ * 16 + (c8 >> 2)];
        uint4 v1 = Qgb[r_ * 16 + (c8 >> 2) + 1];
        *(uint4*)&Qs[r_ * 68 + c8]     = v0;
        *(uint4*)&Qs[r_ * 68 + c8 + 4] = v1;
    }
    if (t < 64) { maxv[t] = -1e30f; cnt[t] = 0; }

    const float* Kg = g_QKV + 8 * BSO + (long long)b * S_ * O_;
    const float* Vg = g_QKV + 9 * BSO + (long long)b * S_ * O_;
    const __nv_bfloat16* Kgb = g_QKVb + 8 * BSO + (long long)b * S_ * O_;
    const float scale = 0.08838834764831845f;

    const uint32_t ksb = smem_u32(Ks);
    auto fillK = [&](int kt, int buf) {
        uint32_t dst = ksb + (buf * 64 * 68 + r_ * 68 + c8) * 4;
        const __nv_bfloat16* src = Kgb + ((long long)(kt * 64 + r_) * O_) + c8 * 2;
        cp16(dst, src);
        cp16(dst + 16, src + 8);
    };

    const int w = t >> 5, lane = t & 31;
    const int g = lane >> 2, tq = lane & 3;
    const int qb = (w >> 2) << 4, kb = (w & 3) << 4;

    fillK(0, 0);
    CP_COMMIT();

    for (int kt = 0; kt < S_ / 64; kt++) {
        const int cur = kt & 1;
        CP_WAIT0();
        __syncthreads();
        if (kt + 1 < S_ / 64) {
            fillK(kt + 1, cur ^ 1);
            CP_COMMIT();
        }

        {
            const uint32_t* Kb32 = Ks + cur * 64 * 68;
            float d0[4] = {0.f, 0.f, 0.f, 0.f};
            float d1[4] = {0.f, 0.f, 0.f, 0.f};
#pragma unroll
            for (int kc = 0; kc < 8; kc++) {
                const int co = kc * 8 + tq;
                uint32_t a0 = Qs[(qb + g) * 68 + co];
                uint32_t a1 = Qs[(qb + g + 8) * 68 + co];
                uint32_t a2 = Qs[(qb + g) * 68 + co + 4];
                uint32_t a3 = Qs[(qb + g + 8) * 68 + co + 4];
                uint32_t b0 = Kb32[(kb + g) * 68 + co];
                uint32_t b1 = Kb32[(kb + g) * 68 + co + 4];
                uint32_t b2 = Kb32[(kb + 8 + g) * 68 + co];
                uint32_t b3 = Kb32[(kb + 8 + g) * 68 + co + 4];
                mma_bf16(d0, a0, a1, a2, a3, b0, b1);
                mma_bf16(d1, a0, a1, a2, a3, b2, b3);
            }
            *(float2*)&Sc[(qb + g) * 68 + kb + 2 * tq] =
                make_float2(d0[0] * scale, d0[1] * scale);
            *(float2*)&Sc[(qb + g + 8) * 68 + kb + 2 * tq] =
                make_float2(d0[2] * scale, d0[3] * scale);
            *(float2*)&Sc[(qb + g) * 68 + kb + 8 + 2 * tq] =
                make_float2(d1[0] * scale, d1[1] * scale);
            *(float2*)&Sc[(qb + g + 8) * 68 + kb + 8 + 2 * tq] =
                make_float2(d1[2] * scale, d1[3] * scale);
        }
        __syncthreads();

        if (t < 64) {
            float mx = maxv[t];
            int c = cnt[t];
            float thr = mx - FMARGIN;
            const float4* sr = (const float4*)&Sc[t * 68];
            float* cS = &candS[t * CAP];
            int*   cK = &candK[t * CAP];
#pragma unroll 4
            for (int j4 = 0; j4 < 16; j4++) {
                float4 v = sr[j4];
                float m4 = fmaxf(fmaxf(v.x, v.y), fmaxf(v.z, v.w));
                if (m4 > thr) {
                    float ss[4] = {v.x, v.y, v.z, v.w};
#pragma unroll
                    for (int u = 0; u < 4; u++) {
                        float s = ss[u];
                        if (s > thr) {
                            if (s > mx) { mx = s; thr = mx - FMARGIN; }
                            if (c == CAP) {
                                int wj = 0;
                                for (int i = 0; i < CAP; i++)
                                    if (cS[i] > thr) {
                                        cS[wj] = cS[i]; cK[wj] = cK[i]; wj++;
                                    }
                                c = wj;
                            }
                            if (c < CAP) {
                                cS[c] = s; cK[c] = kt * 64 + j4 * 4 + u; c++;
                            } else {
                                int am = 0; float mv = cS[0];
                                for (int i = 1; i < CAP; i++)
                                    if (cS[i] < mv) { mv = cS[i]; am = i; }
                                if (s > mv) { cS[am] = s; cK[am] = kt * 64 + j4 * 4 + u; }
                            }
                        }
                    }
                }
            }
            maxv[t] = mx; cnt[t] = c;
        }
        __syncthreads();
    }

    // Final: exact fp32 re-check + softmax + V gather
    const float* Qg = g_QKV + (long long)h * BSO + ((long long)b * S_ + q0) * O_;
#pragma unroll
    for (int i = 0; i < 4; i++) {
        const int r = 4 * w + i;
        const int c = cnt[r];
        float* cS = &candS[r * CAP];
        int*   cK = &candK[r * CAP];
        const float4 qv = ((const float4*)(Qg + (long long)r * O_))[lane];

        for (int idx = 0; idx < c; idx++) {
            const float4 kv = ((const float4*)(Kg + (long long)cK[idx] * O_))[lane];
            float d = qv.x * kv.x + qv.y * kv.y + qv.z * kv.z + qv.w * kv.w;
#pragma unroll
            for (int o = 16; o; o >>= 1) d += __shfl_xor_sync(~0u, d, o);
            if (lane == 0) cS[idx] = d * scale;
        }
        __syncwarp();

        float mx = -1e30f;
        for (int idx = 0; idx < c; idx++) mx = fmaxf(mx, cS[idx]);

        float4 a = make_float4(0.f, 0.f, 0.f, 0.f);
        float l = 0.f;
        for (int idx = 0; idx < c; idx++) {
            float s = cS[idx];
            if (s < mx - THRESH) continue;
            float p = __expf(s - mx);
            const float4 v = ((const float4*)(Vg + (long long)cK[idx] * O_))[lane];
            l += p;
            a.x += p * v.x; a.y += p * v.y; a.z += p * v.z; a.w += p * v.w;
        }
        const float inv = 1.0f / l;
        float* cp = &g_ctx[(((long long)b * S_ + q0 + r) * H_ + h) * O_ + lane * 4];
        *(float4*)cp = make_float4(a.x * inv, a.y * inv, a.z * inv, a.w * inv);
    }
}

// ---------------------------------------------------------------------------
extern "C" void kernel_launch(void* const* d_in, const int* in_sizes, int n_in,
                              void* d_out, int out_size)
{
    const float* x  = (const float*)d_in[0];
    const float* Wq = (const float*)d_in[1];
    const float* Wk = (const float*)d_in[2];
    const float* Wv = (const float*)d_in[3];
    const float* Wo = (const float*)d_in[4];
    float* out = (float*)d_out;

    float *QKVp, *Cp;
    __nv_bfloat16 *QKVb;
    __half *xh, *xl, *ch, *cl, *wT, *wo;
    cudaGetSymbolAddress((void**)&QKVp, g_QKV);
    cudaGetSymbolAddress((void**)&QKVb, g_QKVb);
    cudaGetSymbolAddress((void**)&Cp, g_ctx);
    cudaGetSymbolAddress((void**)&xh, g_xh);
    cudaGetSymbolAddress((void**)&xl, g_xl);
    cudaGetSymbolAddress((void**)&ch, g_ch);
    cudaGetSymbolAddress((void**)&cl, g_cl);
    cudaGetSymbolAddress((void**)&wT, g_wT);
    cudaGetSymbolAddress((void**)&wo, g_woT);

    const size_t wH  = (size_t)NMAT * O_ * E_;      // hi/lo half offset (QKV)
    const size_t woH = (size_t)E_ * H_ * O_;
    const size_t OE  = (size_t)O_ * E_;

    cudaFuncSetAttribute(hgemm3,
                         cudaFuncAttributeMaxDynamicSharedMemorySize, HG_SMEM);
    cudaFuncSetAttribute(attn_kernel,
                         cudaFuncAttributeMaxDynamicSharedMemorySize, ATTN_SMEM);

    const int M = B_ * S_;  // 8192
    const int nX = M * E_;  // 8.4M

    // A-operand split: x -> fp16 hi/lo (once, reused by all 10 projections)
    split_h<<<nX / 4 / 256, 256>>>(x, xh, xl, nX);

    // Weight transpose + fp16 split into fused layout [z][N][K]
    transpose_split_h<<<dim3(O_ / 32, E_ / 32, H_), dim3(32, 8)>>>(
        Wq, wT, wT + wH, E_, O_, (long long)E_ * O_, (long long)OE);
    transpose_split_h<<<dim3(O_ / 32, E_ / 32, 1), dim3(32, 8)>>>(
        Wk, wT + 8 * OE, wT + wH + 8 * OE, E_, O_, 0, 0);
    transpose_split_h<<<dim3(O_ / 32, E_ / 32, 1), dim3(32, 8)>>>(
        Wv, wT + 9 * OE, wT + wH + 9 * OE, E_, O_, 0, 0);
    transpose_split_h<<<dim3(E_ / 32, (H_ * O_) / 32, 1), dim3(32, 8)>>>(
        Wo, wo, wo + woH, H_ * O_, E_, 0, 0);

    // Fused Q/K/V projections: one GEMM, Ntot = 1280 (10 slices of 128),
    // z-sliced epilogue + bf16 copies
    hgemm3<<<dim3(NMAT * O_ / 128, M / 256), 256, HG_SMEM>>>(
        xh, xl, wT, wT + wH, QKVp, QKVb, E_, NMAT * O_, 1);

    // Attention (bf16 HMMA filter + exact re-check + gather)
    attn_kernel<<<dim3(S_ / 64, H_, B_), 512, ATTN_SMEM>>>();

    // ctx split + output projection: (B*S, H*O) @ (H*O, E) -> d_out
    const int nC = M * H_ * O_;
    split_h<<<nC / 4 / 256, 256>>>(Cp, ch, cl, nC);
    hgemm3<<<dim3(E_ / 128, M / 256), 256, HG_SMEM>>>(
        ch, cl, wo, wo + woH, out, (__nv_bfloat16*)0, H_ * O_, E_, 0);
}

// round 15
// speedup vs baseline: 1.1653x; 1.0697x over previous
#include <cuda_runtime.h>
#include <cuda_fp16.h>
#include <cuda_bf16.h>
#include <cstdint>

// Problem constants
#define B_ 4
#define S_ 2048
#define E_ 1024
#define H_ 8
#define O_ 128

#define BSO ((size_t)B_ * S_ * O_)       // 1,048,576
#define NMAT (H_ + 2)                    // 8 Q heads + K + V

// Scratch (allocation-free: __device__ globals)
__device__ float g_QKV[NMAT * BSO];              // z<8: Q head z; 8: K; 9: V
__device__ __nv_bfloat16 g_QKVb[NMAT * BSO];     // bf16 copies (filter pass)
// fp16 hi/lo splits of GEMM A operands
__device__ __half g_xh[(size_t)B_ * S_ * E_];
__device__ __half g_xl[(size_t)B_ * S_ * E_];
__device__ __half g_ch[(size_t)B_ * S_ * H_ * O_];   // ctx hi (from attn)
__device__ __half g_cl[(size_t)B_ * S_ * H_ * O_];   // ctx lo (from attn)
// Transposed + fp16-split weights, layout [N][K]: QKV fused, Wo separate
__device__ __half g_wT[2][(size_t)NMAT * O_ * E_];
__device__ __half g_woT[2][(size_t)E_ * H_ * O_];

// ---------------------------------------------------------------------------
__device__ __forceinline__ void cp16(uint32_t dst, const void* src) {
    asm volatile("cp.async.ca.shared.global [%0], [%1], 16;"
                 :: "r"(dst), "l"(src));
}
#define CP_COMMIT() asm volatile("cp.async.commit_group;" ::: "memory")
#define CP_WAIT0()  asm volatile("cp.async.wait_group 0;" ::: "memory")
#define CP_WAIT1()  asm volatile("cp.async.wait_group 1;" ::: "memory")

__device__ __forceinline__ uint32_t smem_u32(const void* p) {
    uint32_t a;
    asm("{ .reg .u64 t; cvta.to.shared.u64 t, %1; cvt.u32.u64 %0, t; }"
        : "=r"(a) : "l"(p));
    return a;
}

// ldmatrix 4x(8x8) b16 fragments — baseline sm_75 PTX
__device__ __forceinline__ void ldm4(uint32_t* r, uint32_t addr) {
    asm volatile(
        "ldmatrix.sync.aligned.m8n8.x4.shared.b16 {%0,%1,%2,%3}, [%4];"
        : "=r"(r[0]), "=r"(r[1]), "=r"(r[2]), "=r"(r[3]) : "r"(addr));
}

// mma.sync m16n8k16 bf16 — D += A*B, fp32 accumulate (baseline sm_80 PTX)
__device__ __forceinline__ void mma_bf16(float* d,
                                         uint32_t a0, uint32_t a1,
                                         uint32_t a2, uint32_t a3,
                                         uint32_t b0, uint32_t b1) {
    asm volatile(
        "mma.sync.aligned.m16n8k16.row.col.f32.bf16.bf16.f32 "
        "{%0,%1,%2,%3}, {%4,%5,%6,%7}, {%8,%9}, {%0,%1,%2,%3};"
        : "+f"(d[0]), "+f"(d[1]), "+f"(d[2]), "+f"(d[3])
        : "r"(a0), "r"(a1), "r"(a2), "r"(a3), "r"(b0), "r"(b1));
}

// mma.sync m16n8k16 fp16 — D += A*B, fp32 accumulate (baseline sm_80 PTX)
__device__ __forceinline__ void mma_f16(float* d, const uint32_t a[4],
                                        uint32_t b0, uint32_t b1) {
    asm volatile(
        "mma.sync.aligned.m16n8k16.row.col.f32.f16.f16.f32 "
        "{%0,%1,%2,%3}, {%4,%5,%6,%7}, {%8,%9}, {%0,%1,%2,%3};"
        : "+f"(d[0]), "+f"(d[1]), "+f"(d[2]), "+f"(d[3])
        : "r"(a[0]), "r"(a[1]), "r"(a[2]), "r"(a[3]), "r"(b0), "r"(b1));
}

// ---------------------------------------------------------------------------
// fp32 -> fp16 hi/lo split, bulk (n % 4 == 0)
// ---------------------------------------------------------------------------
__global__ void split_h(const float* __restrict__ in,
                        __half* __restrict__ oh, __half* __restrict__ ol,
                        int n)
{
    int i = (blockIdx.x * blockDim.x + threadIdx.x) * 4;
    if (i < n) {
        float4 v = *(const float4*)(in + i);
        __half2 h0 = __floats2half2_rn(v.x, v.y);
        __half2 h1 = __floats2half2_rn(v.z, v.w);
        float2 f0 = __half22float2(h0);
        float2 f1 = __half22float2(h1);
        __half2 l0 = __floats2half2_rn(v.x - f0.x, v.y - f0.y);
        __half2 l1 = __floats2half2_rn(v.z - f1.x, v.w - f1.y);
        *(__half2*)(oh + i)     = h0;
        *(__half2*)(oh + i + 2) = h1;
        *(__half2*)(ol + i)     = l0;
        *(__half2*)(ol + i + 2) = l1;
    }
}

// ---------------------------------------------------------------------------
// Weight transpose + fp16 hi/lo split: in[K][N] (+z*sIn) -> hi/lo [N][K]
// grid (N/32, K/32, Z), block (32, 8)
// ---------------------------------------------------------------------------
__global__ void transpose_split_h(const float* __restrict__ in,
                                  __half* __restrict__ oh,
                                  __half* __restrict__ ol,
                                  int K, int N, long long sIn, long long sOut)
{
    __shared__ float t[32][33];
    const float* ip = in + (long long)blockIdx.z * sIn;
    __half* ph = oh + (long long)blockIdx.z * sOut;
    __half* pl = ol + (long long)blockIdx.z * sOut;
    const int n0 = blockIdx.x * 32, k0 = blockIdx.y * 32;
    const int tx = threadIdx.x, ty = threadIdx.y;
#pragma unroll
    for (int p = 0; p < 4; p++)
        t[ty + 8 * p][tx] = ip[(long long)(k0 + ty + 8 * p) * N + n0 + tx];
    __syncthreads();
#pragma unroll
    for (int p = 0; p < 4; p++) {
        float v = t[tx][ty + 8 * p];
        __half h = __float2half_rn(v);
        __half l = __float2half_rn(v - __half2float(h));
        long long o = (long long)(n0 + ty + 8 * p) * K + k0 + tx;
        ph[o] = h;
        pl[o] = l;
    }
}

// ---------------------------------------------------------------------------
// fp16x2 split GEMM v4 (templated N-tile): ldmatrix + 3-stage cp.async.
// Block tile 256(M) x (16*NJ)(N) x 32(K), 256 threads, 8 warps (4m x 2n),
// warp tile 64 x (8*NJ). C = Ahl @ Bt^T (hh + hl + lh, ~22-bit exact).
// zsplit=1: cols are [z][128] slices of stride BSO; optional bf16 copy Cb.
// ---------------------------------------------------------------------------
#define HS 20                        // u32 stride per smem row (bank-clean)

template <int NJ>
__global__ __launch_bounds__(256, 1) void hgemm3(
    const __half* __restrict__ Ah, const __half* __restrict__ Al,
    const __half* __restrict__ Bth, const __half* __restrict__ Btl,
    float* __restrict__ C, __nv_bfloat16* __restrict__ Cb,
    int K, int Ntot, int zsplit)
{
    constexpr int NT    = 16 * NJ;               // block N-tile
    constexpr int STA_L = 256 * HS;
    constexpr int STB_H = 512 * HS;
    constexpr int STB_L = (512 + NT) * HS;
    constexpr int STAGE = (512 + 2 * NT) * HS;   // u32 per stage
    constexpr int VR    = 512 + 2 * NT;          // virtual fill rows

    extern __shared__ __align__(16) uint32_t su[];
    const int tid = threadIdx.x, w = tid >> 5, lane = tid & 31;
    const int g = lane >> 2, tq = lane & 3;
    const int wm = w & 3, wn = w >> 2;
    const int m0 = blockIdx.y * 256, n0 = blockIdx.x * NT;
    const uint32_t sb = smem_u32(su);
    const int NK = K >> 5;

    // Fill precompute: VR virtual rows, thread handles rows tid + 256*j
    const __half* srcp[4];
    uint32_t dsto[4];
    bool valid[4];
#pragma unroll
    for (int j = 0; j < 4; j++) {
        int vr = tid + (j << 8);
        valid[j] = vr < VR;
        int vc = valid[j] ? vr : 0;
        if (vc < 256)           { srcp[j] = Ah  + (size_t)(m0 + vc) * K;
                                  dsto[j] = vc * HS; }
        else if (vc < 512)      { srcp[j] = Al  + (size_t)(m0 + vc - 256) * K;
                                  dsto[j] = STA_L + (vc - 256) * HS; }
        else if (vc < 512 + NT) { srcp[j] = Bth + (size_t)(n0 + vc - 512) * K;
                                  dsto[j] = STB_H + (vc - 512) * HS; }
        else                    { srcp[j] = Btl + (size_t)(n0 + vc - 512 - NT) * K;
                                  dsto[j] = STB_L + (vc - 512 - NT) * HS; }
    }
    auto fill = [&](int kt, int st) {
#pragma unroll
        for (int j = 0; j < 4; j++) {
            if (!valid[j]) continue;
            const __half* sp = srcp[j] + (kt << 5);
            uint32_t d = sb + (st * STAGE + dsto[j]) * 4;
            cp16(d, sp);           cp16(d + 16, sp + 8);
            cp16(d + 32, sp + 16); cp16(d + 48, sp + 24);
        }
    };

    // ldmatrix lane-relative offsets (u32 units)
    const uint32_t a_ro = (uint32_t)((wm * 64 + (lane & 15)) * HS +
                                     ((lane >> 4) << 2));
    const uint32_t b_ro = (uint32_t)((wn * (8 * NJ) + (lane & 7) +
                                      ((lane >> 4) << 3)) * HS +
                                     (((lane >> 3) & 1) << 2));

    float acc[4][NJ][4];
#pragma unroll
    for (int mi = 0; mi < 4; mi++)
#pragma unroll
        for (int nj = 0; nj < NJ; nj++)
#pragma unroll
            for (int q = 0; q < 4; q++) acc[mi][nj][q] = 0.f;

    // Prologue: stages 0, 1 in flight
    fill(0, 0);
    CP_COMMIT();
    if (NK > 1) { fill(1, 1); CP_COMMIT(); }

    for (int kt = 0; kt < NK; kt++) {
        if (kt + 1 < NK) { CP_WAIT1(); } else { CP_WAIT0(); }
        __syncthreads();                 // stage kt ready; stage (kt+2)%3 free
        if (kt + 2 < NK) {
            fill(kt + 2, (kt + 2) % 3);
            CP_COMMIT();
        }

        const uint32_t stb = sb + ((kt % 3) * STAGE) * 4;
#pragma unroll
        for (int ks = 0; ks < 2; ks++) {
            uint32_t AH[4][4], AL[4][4];
#pragma unroll
            for (int mi = 0; mi < 4; mi++) {
                uint32_t ao = stb + (a_ro + mi * 16 * HS + ks * 8) * 4;
                ldm4(AH[mi], ao);
                ldm4(AL[mi], ao + STA_L * 4);
            }
#pragma unroll
            for (int njp = 0; njp < NJ / 2; njp++) {
                uint32_t BH[4], BL[4];
                uint32_t bo = stb + (STB_H + b_ro + njp * 16 * HS + ks * 8) * 4;
                ldm4(BH, bo);
                ldm4(BL, bo + (STB_L - STB_H) * 4);
#pragma unroll
                for (int mi = 0; mi < 4; mi++) {
                    mma_f16(acc[mi][2 * njp],     AH[mi], BH[0], BH[1]);
                    mma_f16(acc[mi][2 * njp],     AH[mi], BL[0], BL[1]);
                    mma_f16(acc[mi][2 * njp],     AL[mi], BH[0], BH[1]);
                    mma_f16(acc[mi][2 * njp + 1], AH[mi], BH[2], BH[3]);
                    mma_f16(acc[mi][2 * njp + 1], AH[mi], BL[2], BL[3]);
                    mma_f16(acc[mi][2 * njp + 1], AL[mi], BH[2], BH[3]);
                }
            }
        }
    }

    // Epilogue
#pragma unroll
    for (int mi = 0; mi < 4; mi++) {
#pragma unroll
        for (int nj = 0; nj < NJ; nj++) {
            int r0 = m0 + wm * 64 + mi * 16 + g;
            int cg = n0 + wn * (8 * NJ) + nj * 8 + 2 * tq;
            float* base;
            long long rs;
            __nv_bfloat16* bb = 0;
            if (zsplit) {
                int z = cg >> 7, o = cg & 127;
                base = C + (size_t)z * BSO + (size_t)r0 * 128 + o;
                rs = 128;
                if (Cb) bb = Cb + (size_t)z * BSO + (size_t)r0 * 128 + o;
            } else {
                base = C + (size_t)r0 * Ntot + cg;
                rs = Ntot;
            }
            float2 v0 = make_float2(acc[mi][nj][0], acc[mi][nj][1]);
            float2 v1 = make_float2(acc[mi][nj][2], acc[mi][nj][3]);
            *(float2*)base = v0;
            *(float2*)(base + 8 * rs) = v1;
            if (bb) {
                *(__nv_bfloat162*)bb = __floats2bfloat162_rn(v0.x, v0.y);
                *(__nv_bfloat162*)(bb + 8 * rs) =
                    __floats2bfloat162_rn(v1.x, v1.y);
            }
        }
    }
}

// ---------------------------------------------------------------------------
// Attention: bf16 HMMA filter + exact fp32 re-check; epilogue writes ctx
// directly as fp16 hi/lo (for the Wo GEMM). grid (S/64, H, B), 512 threads.
// ---------------------------------------------------------------------------
#define CAP 32
#define THRESH  40.0f
#define FMARGIN 170.0f
#define ATTN_SMEM ((3 * 64 * 68 + 64 * 68 + 64 + 64 * CAP + 64 + 64 * CAP) * 4)

__global__ __launch_bounds__(512) void attn_kernel()
{
    extern __shared__ __align__(16) uint32_t smu[];
    uint32_t* Qs   = smu;                       // 64 x 68 u32 (bf16 pairs)
    uint32_t* Ks   = Qs + 64 * 68;              // 2 x 64 x 68 u32
    float*    Sc   = (float*)(Ks + 2 * 64 * 68);// 64 x 68 approx scores
    float*    maxv = Sc + 64 * 68;              // 64
    float*    candS= maxv + 64;                 // 64 x CAP
    int*      cnt  = (int*)(candS + 64 * CAP);  // 64
    int*      candK= cnt + 64;                  // 64 x CAP

    const int t  = threadIdx.x;
    const int q0 = blockIdx.x * 64;
    const int h  = blockIdx.y;
    const int b  = blockIdx.z;

    const int r_ = t >> 3;
    const int c8 = (t & 7) << 3;

    {
        const uint4* Qgb = (const uint4*)(g_QKVb +
            ((long long)h * BSO + ((long long)b * S_ + q0) * O_));
        uint4 v0 = Qgb[r_ * 16 + (c8 >> 2)];
        uint4 v1 = Qgb[r_ * 16 + (c8 >> 2) + 1];
        *(uint4*)&Qs[r_ * 68 + c8]     = v0;
        *(uint4*)&Qs[r_ * 68 + c8 + 4] = v1;
    }
    if (t < 64) { maxv[t] = -1e30f; cnt[t] = 0; }

    const float* Kg = g_QKV + 8 * BSO + (long long)b * S_ * O_;
    const float* Vg = g_QKV + 9 * BSO + (long long)b * S_ * O_;
    const __nv_bfloat16* Kgb = g_QKVb + 8 * BSO + (long long)b * S_ * O_;
    const float scale = 0.08838834764831845f;

    const uint32_t ksb = smem_u32(Ks);
    auto fillK = [&](int kt, int buf) {
        uint32_t dst = ksb + (buf * 64 * 68 + r_ * 68 + c8) * 4;
        const __nv_bfloat16* src = Kgb + ((long long)(kt * 64 + r_) * O_) + c8 * 2;
        cp16(dst, src);
        cp16(dst + 16, src + 8);
    };

    const int w = t >> 5, lane = t & 31;
    const int g = lane >> 2, tq = lane & 3;
    const int qb = (w >> 2) << 4, kb = (w & 3) << 4;

    fillK(0, 0);
    CP_COMMIT();

    for (int kt = 0; kt < S_ / 64; kt++) {
        const int cur = kt & 1;
        CP_WAIT0();
        __syncthreads();
        if (kt + 1 < S_ / 64) {
            fillK(kt + 1, cur ^ 1);
            CP_COMMIT();
        }

        {
            const uint32_t* Kb32 = Ks + cur * 64 * 68;
            float d0[4] = {0.f, 0.f, 0.f, 0.f};
            float d1[4] = {0.f, 0.f, 0.f, 0.f};
#pragma unroll
            for (int kc = 0; kc < 8; kc++) {
                const int co = kc * 8 + tq;
                uint32_t a0 = Qs[(qb + g) * 68 + co];
                uint32_t a1 = Qs[(qb + g + 8) * 68 + co];
                uint32_t a2 = Qs[(qb + g) * 68 + co + 4];
                uint32_t a3 = Qs[(qb + g + 8) * 68 + co + 4];
                uint32_t b0 = Kb32[(kb + g) * 68 + co];
                uint32_t b1 = Kb32[(kb + g) * 68 + co + 4];
                uint32_t b2 = Kb32[(kb + 8 + g) * 68 + co];
                uint32_t b3 = Kb32[(kb + 8 + g) * 68 + co + 4];
                mma_bf16(d0, a0, a1, a2, a3, b0, b1);
                mma_bf16(d1, a0, a1, a2, a3, b2, b3);
            }
            *(float2*)&Sc[(qb + g) * 68 + kb + 2 * tq] =
                make_float2(d0[0] * scale, d0[1] * scale);
            *(float2*)&Sc[(qb + g + 8) * 68 + kb + 2 * tq] =
                make_float2(d0[2] * scale, d0[3] * scale);
            *(float2*)&Sc[(qb + g) * 68 + kb + 8 + 2 * tq] =
                make_float2(d1[0] * scale, d1[1] * scale);
            *(float2*)&Sc[(qb + g + 8) * 68 + kb + 8 + 2 * tq] =
                make_float2(d1[2] * scale, d1[3] * scale);
        }
        __syncthreads();

        if (t < 64) {
            float mx = maxv[t];
            int c = cnt[t];
            float thr = mx - FMARGIN;
            const float4* sr = (const float4*)&Sc[t * 68];
            float* cS = &candS[t * CAP];
            int*   cK = &candK[t * CAP];
#pragma unroll 4
            for (int j4 = 0; j4 < 16; j4++) {
                float4 v = sr[j4];
                float m4 = fmaxf(fmaxf(v.x, v.y), fmaxf(v.z, v.w));
                if (m4 > thr) {
                    float ss[4] = {v.x, v.y, v.z, v.w};
#pragma unroll
                    for (int u = 0; u < 4; u++) {
                        float s = ss[u];
                        if (s > thr) {
                            if (s > mx) { mx = s; thr = mx - FMARGIN; }
                            if (c == CAP) {
                                int wj = 0;
                                for (int i = 0; i < CAP; i++)
                                    if (cS[i] > thr) {
                                        cS[wj] = cS[i]; cK[wj] = cK[i]; wj++;
                                    }
                                c = wj;
                            }
                            if (c < CAP) {
                                cS[c] = s; cK[c] = kt * 64 + j4 * 4 + u; c++;
                            } else {
                                int am = 0; float mv = cS[0];
                                for (int i = 1; i < CAP; i++)
                                    if (cS[i] < mv) { mv = cS[i]; am = i; }
                                if (s > mv) { cS[am] = s; cK[am] = kt * 64 + j4 * 4 + u; }
                            }
                        }
                    }
                }
            }
            maxv[t] = mx; cnt[t] = c;
        }
        __syncthreads();
    }

    // Final: exact fp32 re-check + softmax + V gather; write ctx hi/lo fp16
    const float* Qg = g_QKV + (long long)h * BSO + ((long long)b * S_ + q0) * O_;
#pragma unroll
    for (int i = 0; i < 4; i++) {
        const int r = 4 * w + i;
        const int c = cnt[r];
        float* cS = &candS[r * CAP];
        int*   cK = &candK[r * CAP];
        const float4 qv = ((const float4*)(Qg + (long long)r * O_))[lane];

        for (int idx = 0; idx < c; idx++) {
            const float4 kv = ((const float4*)(Kg + (long long)cK[idx] * O_))[lane];
            float d = qv.x * kv.x + qv.y * kv.y + qv.z * kv.z + qv.w * kv.w;
#pragma unroll
            for (int o = 16; o; o >>= 1) d += __shfl_xor_sync(~0u, d, o);
            if (lane == 0) cS[idx] = d * scale;
        }
        __syncwarp();

        float mx = -1e30f;
        for (int idx = 0; idx < c; idx++) mx = fmaxf(mx, cS[idx]);

        float4 a = make_float4(0.f, 0.f, 0.f, 0.f);
        float l = 0.f;
        for (int idx = 0; idx < c; idx++) {
            float s = cS[idx];
            if (s < mx - THRESH) continue;
            float p = __expf(s - mx);
            const float4 v = ((const float4*)(Vg + (long long)cK[idx] * O_))[lane];
            l += p;
            a.x += p * v.x; a.y += p * v.y; a.z += p * v.z; a.w += p * v.w;
        }
        const float inv = 1.0f / l;
        float4 r4 = make_float4(a.x * inv, a.y * inv, a.z * inv, a.w * inv);

        // fp16 hi/lo split of ctx, written directly for the Wo GEMM
        size_t ci = (((size_t)b * S_ + q0 + r) * H_ + h) * O_ + lane * 4;
        __half2 h0 = __floats2half2_rn(r4.x, r4.y);
        __half2 h1 = __floats2half2_rn(r4.z, r4.w);
        float2 f0 = __half22float2(h0);
        float2 f1 = __half22float2(h1);
        __half2 l0 = __floats2half2_rn(r4.x - f0.x, r4.y - f0.y);
        __half2 l1 = __floats2half2_rn(r4.z - f1.x, r4.w - f1.y);
        *(__half2*)(g_ch + ci)     = h0;
        *(__half2*)(g_ch + ci + 2) = h1;
        *(__half2*)(g_cl + ci)     = l0;
        *(__half2*)(g_cl + ci + 2) = l1;
    }
}

// ---------------------------------------------------------------------------
extern "C" void kernel_launch(void* const* d_in, const int* in_sizes, int n_in,
                              void* d_out, int out_size)
{
    const float* x  = (const float*)d_in[0];
    const float* Wq = (const float*)d_in[1];
    const float* Wk = (const float*)d_in[2];
    const float* Wv = (const float*)d_in[3];
    const float* Wo = (const float*)d_in[4];
    float* out = (float*)d_out;

    float *QKVp;
    __nv_bfloat16 *QKVb;
    __half *xh, *xl, *ch, *cl, *wT, *wo;
    cudaGetSymbolAddress((void**)&QKVp, g_QKV);
    cudaGetSymbolAddress((void**)&QKVb, g_QKVb);
    cudaGetSymbolAddress((void**)&xh, g_xh);
    cudaGetSymbolAddress((void**)&xl, g_xl);
    cudaGetSymbolAddress((void**)&ch, g_ch);
    cudaGetSymbolAddress((void**)&cl, g_cl);
    cudaGetSymbolAddress((void**)&wT, g_wT);
    cudaGetSymbolAddress((void**)&wo, g_woT);

    const size_t wH  = (size_t)NMAT * O_ * E_;      // hi/lo half offset (QKV)
    const size_t woH = (size_t)E_ * H_ * O_;
    const size_t OE  = (size_t)O_ * E_;

    // smem sizes per template instantiation
    const int SM10 = 3 * (512 + 2 * 160) * HS * 4;  // NJ=10: 199680 B
    const int SM8  = 3 * (512 + 2 * 128) * HS * 4;  // NJ=8 : 184320 B
    cudaFuncSetAttribute(hgemm3<10>,
                         cudaFuncAttributeMaxDynamicSharedMemorySize, SM10);
    cudaFuncSetAttribute(hgemm3<8>,
                         cudaFuncAttributeMaxDynamicSharedMemorySize, SM8);
    cudaFuncSetAttribute(attn_kernel,
                         cudaFuncAttributeMaxDynamicSharedMemorySize, ATTN_SMEM);

    const int M = B_ * S_;  // 8192
    const int nX = M * E_;  // 8.4M

    // A-operand split: x -> fp16 hi/lo (once, reused by all 10 projections)
    split_h<<<nX / 4 / 256, 256>>>(x, xh, xl, nX);

    // Weight transpose + fp16 split into fused layout [z][N][K]
    transpose_split_h<<<dim3(O_ / 32, E_ / 32, H_), dim3(32, 8)>>>(
        Wq, wT, wT + wH, E_, O_, (long long)E_ * O_, (long long)OE);
    transpose_split_h<<<dim3(O_ / 32, E_ / 32, 1), dim3(32, 8)>>>(
        Wk, wT + 8 * OE, wT + wH + 8 * OE, E_, O_, 0, 0);
    transpose_split_h<<<dim3(O_ / 32, E_ / 32, 1), dim3(32, 8)>>>(
        Wv, wT + 9 * OE, wT + wH + 9 * OE, E_, O_, 0, 0);
    transpose_split_h<<<dim3(E_ / 32, (H_ * O_) / 32, 1), dim3(32, 8)>>>(
        Wo, wo, wo + woH, H_ * O_, E_, 0, 0);

    // Fused Q/K/V projections: Ntot = 1280, N-tile 160 -> 8 x 32 = 256 blocks
    hgemm3<10><<<dim3(NMAT * O_ / 160, M / 256), 256, SM10>>>(
        xh, xl, wT, wT + wH, QKVp, QKVb, E_, NMAT * O_, 1);

    // Attention (bf16 HMMA filter + exact re-check + gather; writes ch/cl)
    attn_kernel<<<dim3(S_ / 64, H_, B_), 512, ATTN_SMEM>>>();

    // Output projection: (B*S, H*O) @ (H*O, E) -> d_out
    hgemm3<8><<<dim3(E_ / 128, M / 256), 256, SM8>>>(
        ch, cl, wo, wo + woH, out, (__nv_bfloat16*)0, H_ * O_, E_, 0);
}

// round 16
// speedup vs baseline: 1.2962x; 1.1123x over previous
#include <cuda_runtime.h>
#include <cuda_fp16.h>
#include <cuda_bf16.h>
#include <cstdint>

// Problem constants
#define B_ 4
#define S_ 2048
#define E_ 1024
#define H_ 8
#define O_ 128

#define BSO ((size_t)B_ * S_ * O_)       // 1,048,576
#define NMAT (H_ + 2)                    // 8 Q heads + K + V

// Scratch (allocation-free: __device__ globals)
__device__ float g_QKV[NMAT * BSO];              // z<8: Q head z; 8: K; 9: V
__device__ __half g_QKVh[NMAT * BSO];            // fp16 copies (filter pass;
                                                 //  Q slices pre-scaled)
// fp16 hi/lo splits of GEMM A operands
__device__ __half g_xh[(size_t)B_ * S_ * E_];
__device__ __half g_xl[(size_t)B_ * S_ * E_];
__device__ __half g_ch[(size_t)B_ * S_ * H_ * O_];   // ctx hi (from attn)
// Transposed + fp16-split weights, layout [N][K]: QKV fused, Wo separate
__device__ __half g_wT[2][(size_t)NMAT * O_ * E_];
__device__ __half g_woT[2][(size_t)E_ * H_ * O_];

#define QSCALE 0.08838834764831845f     // 1/sqrt(128)

// ---------------------------------------------------------------------------
__device__ __forceinline__ void cp16(uint32_t dst, const void* src) {
    asm volatile("cp.async.ca.shared.global [%0], [%1], 16;"
                 :: "r"(dst), "l"(src));
}
#define CP_COMMIT() asm volatile("cp.async.commit_group;" ::: "memory")
#define CP_WAIT0()  asm volatile("cp.async.wait_group 0;" ::: "memory")
#define CP_WAIT1()  asm volatile("cp.async.wait_group 1;" ::: "memory")

__device__ __forceinline__ uint32_t smem_u32(const void* p) {
    uint32_t a;
    asm("{ .reg .u64 t; cvta.to.shared.u64 t, %1; cvt.u32.u64 %0, t; }"
        : "=r"(a) : "l"(p));
    return a;
}

// ldmatrix 4x(8x8) b16 fragments — baseline sm_75 PTX
__device__ __forceinline__ void ldm4(uint32_t* r, uint32_t addr) {
    asm volatile(
        "ldmatrix.sync.aligned.m8n8.x4.shared.b16 {%0,%1,%2,%3}, [%4];"
        : "=r"(r[0]), "=r"(r[1]), "=r"(r[2]), "=r"(r[3]) : "r"(addr));
}

// mma.sync m16n8k16 fp16 — D += A*B, fp32 accumulate (baseline sm_80 PTX)
__device__ __forceinline__ void mma_f16(float* d, const uint32_t a[4],
                                        uint32_t b0, uint32_t b1) {
    asm volatile(
        "mma.sync.aligned.m16n8k16.row.col.f32.f16.f16.f32 "
        "{%0,%1,%2,%3}, {%4,%5,%6,%7}, {%8,%9}, {%0,%1,%2,%3};"
        : "+f"(d[0]), "+f"(d[1]), "+f"(d[2]), "+f"(d[3])
        : "r"(a[0]), "r"(a[1]), "r"(a[2]), "r"(a[3]), "r"(b0), "r"(b1));
}

// mma.sync m16n8k16 fp16 — D += A*B, fp16 accumulate (2x rate on legacy HMMA)
__device__ __forceinline__ void mma_f16acc(uint32_t* d,
                                           uint32_t a0, uint32_t a1,
                                           uint32_t a2, uint32_t a3,
                                           uint32_t b0, uint32_t b1) {
    asm volatile(
        "mma.sync.aligned.m16n8k16.row.col.f16.f16.f16.f16 "
        "{%0,%1}, {%2,%3,%4,%5}, {%6,%7}, {%0,%1};"
        : "+r"(d[0]), "+r"(d[1])
        : "r"(a0), "r"(a1), "r"(a2), "r"(a3), "r"(b0), "r"(b1));
}

// ---------------------------------------------------------------------------
// fp32 -> fp16 hi/lo split, bulk (n % 4 == 0)
// ---------------------------------------------------------------------------
__global__ void split_h(const float* __restrict__ in,
                        __half* __restrict__ oh, __half* __restrict__ ol,
                        int n)
{
    int i = (blockIdx.x * blockDim.x + threadIdx.x) * 4;
    if (i < n) {
        float4 v = *(const float4*)(in + i);
        __half2 h0 = __floats2half2_rn(v.x, v.y);
        __half2 h1 = __floats2half2_rn(v.z, v.w);
        float2 f0 = __half22float2(h0);
        float2 f1 = __half22float2(h1);
        __half2 l0 = __floats2half2_rn(v.x - f0.x, v.y - f0.y);
        __half2 l1 = __floats2half2_rn(v.z - f1.x, v.w - f1.y);
        *(__half2*)(oh + i)     = h0;
        *(__half2*)(oh + i + 2) = h1;
        *(__half2*)(ol + i)     = l0;
        *(__half2*)(ol + i + 2) = l1;
    }
}

// ---------------------------------------------------------------------------
// Weight transpose + fp16 hi/lo split: in[K][N] (+z*sIn) -> hi/lo [N][K]
// grid (N/32, K/32, Z), block (32, 8)
// ---------------------------------------------------------------------------
__global__ void transpose_split_h(const float* __restrict__ in,
                                  __half* __restrict__ oh,
                                  __half* __restrict__ ol,
                                  int K, int N, long long sIn, long long sOut)
{
    __shared__ float t[32][33];
    const float* ip = in + (long long)blockIdx.z * sIn;
    __half* ph = oh + (long long)blockIdx.z * sOut;
    __half* pl = ol + (long long)blockIdx.z * sOut;
    const int n0 = blockIdx.x * 32, k0 = blockIdx.y * 32;
    const int tx = threadIdx.x, ty = threadIdx.y;
#pragma unroll
    for (int p = 0; p < 4; p++)
        t[ty + 8 * p][tx] = ip[(long long)(k0 + ty + 8 * p) * N + n0 + tx];
    __syncthreads();
#pragma unroll
    for (int p = 0; p < 4; p++) {
        float v = t[tx][ty + 8 * p];
        __half h = __float2half_rn(v);
        __half l = __float2half_rn(v - __half2float(h));
        long long o = (long long)(n0 + ty + 8 * p) * K + k0 + tx;
        ph[o] = h;
        pl[o] = l;
    }
}

// ---------------------------------------------------------------------------
// fp16 split GEMM v5 (templated N-tile + product count):
// Block tile 256(M) x (16*NJ)(N) x 32(K), 256 threads, 8 warps (4m x 2n).
// TP=true : 3 products (Ah,Al x Bh,Bl: hh+hl+lh, ~22-bit exact)
// TP=false: 2 products (Ah x Bh,Bl: A treated as fp16-exact)
// zsplit=1: cols are [z][128] slices of stride BSO; fp16 copy Cf (Q pre-scaled)
// ---------------------------------------------------------------------------
#define HS 20                        // u32 stride per smem row (bank-clean)

template <int NJ, bool TP>
__global__ __launch_bounds__(256, 1) void hgemm3(
    const __half* __restrict__ Ah, const __half* __restrict__ Al,
    const __half* __restrict__ Bth, const __half* __restrict__ Btl,
    float* __restrict__ C, __half* __restrict__ Cf,
    int K, int Ntot, int zsplit)
{
    constexpr int NT    = 16 * NJ;               // block N-tile
    constexpr int NA    = TP ? 512 : 256;        // A rows in smem (hi[+lo])
    constexpr int STA_L = 256 * HS;              // (only used if TP)
    constexpr int STB_H = NA * HS;
    constexpr int STB_L = (NA + NT) * HS;
    constexpr int STAGE = (NA + 2 * NT) * HS;    // u32 per stage
    constexpr int VR    = NA + 2 * NT;           // virtual fill rows
    constexpr int NFJ   = (VR + 255) / 256;

    extern __shared__ __align__(16) uint32_t su[];
    const int tid = threadIdx.x, w = tid >> 5, lane = tid & 31;
    const int g = lane >> 2, tq = lane & 3;
    const int wm = w & 3, wn = w >> 2;
    const int m0 = blockIdx.y * 256, n0 = blockIdx.x * NT;
    const uint32_t sb = smem_u32(su);
    const int NK = K >> 5;

    // Fill precompute: VR virtual rows, thread handles rows tid + 256*j
    const __half* srcp[NFJ];
    uint32_t dsto[NFJ];
    bool valid[NFJ];
#pragma unroll
    for (int j = 0; j < NFJ; j++) {
        int vr = tid + (j << 8);
        valid[j] = vr < VR;
        int vc = valid[j] ? vr : 0;
        if (vc < 256)           { srcp[j] = Ah  + (size_t)(m0 + vc) * K;
                                  dsto[j] = vc * HS; }
        else if (TP && vc < 512){ srcp[j] = Al  + (size_t)(m0 + vc - 256) * K;
                                  dsto[j] = STA_L + (vc - 256) * HS; }
        else if (vc < NA + NT)  { srcp[j] = Bth + (size_t)(n0 + vc - NA) * K;
                                  dsto[j] = STB_H + (vc - NA) * HS; }
        else                    { srcp[j] = Btl + (size_t)(n0 + vc - NA - NT) * K;
                                  dsto[j] = STB_L + (vc - NA - NT) * HS; }
    }
    auto fill = [&](int kt, int st) {
#pragma unroll
        for (int j = 0; j < NFJ; j++) {
            if (!valid[j]) continue;
            const __half* sp = srcp[j] + (kt << 5);
            uint32_t d = sb + (st * STAGE + dsto[j]) * 4;
            cp16(d, sp);           cp16(d + 16, sp + 8);
            cp16(d + 32, sp + 16); cp16(d + 48, sp + 24);
        }
    };

    // ldmatrix lane-relative offsets (u32 units)
    const uint32_t a_ro = (uint32_t)((wm * 64 + (lane & 15)) * HS +
                                     ((lane >> 4) << 2));
    const uint32_t b_ro = (uint32_t)((wn * (8 * NJ) + (lane & 7) +
                                      ((lane >> 4) << 3)) * HS +
                                     (((lane >> 3) & 1) << 2));

    float acc[4][NJ][4];
#pragma unroll
    for (int mi = 0; mi < 4; mi++)
#pragma unroll
        for (int nj = 0; nj < NJ; nj++)
#pragma unroll
            for (int q = 0; q < 4; q++) acc[mi][nj][q] = 0.f;

    // Prologue: stages 0, 1 in flight
    fill(0, 0);
    CP_COMMIT();
    if (NK > 1) { fill(1, 1); CP_COMMIT(); }

    for (int kt = 0; kt < NK; kt++) {
        if (kt + 1 < NK) { CP_WAIT1(); } else { CP_WAIT0(); }
        __syncthreads();                 // stage kt ready; stage (kt+2)%3 free
        if (kt + 2 < NK) {
            fill(kt + 2, (kt + 2) % 3);
            CP_COMMIT();
        }

        const uint32_t stb = sb + ((kt % 3) * STAGE) * 4;
#pragma unroll
        for (int ks = 0; ks < 2; ks++) {
            uint32_t AH[4][4], AL[4][4];
#pragma unroll
            for (int mi = 0; mi < 4; mi++) {
                uint32_t ao = stb + (a_ro + mi * 16 * HS + ks * 8) * 4;
                ldm4(AH[mi], ao);
                if (TP) ldm4(AL[mi], ao + STA_L * 4);
            }
#pragma unroll
            for (int njp = 0; njp < NJ / 2; njp++) {
                uint32_t BH[4], BL[4];
                uint32_t bo = stb + (STB_H + b_ro + njp * 16 * HS + ks * 8) * 4;
                ldm4(BH, bo);
                ldm4(BL, bo + (STB_L - STB_H) * 4);
#pragma unroll
                for (int mi = 0; mi < 4; mi++) {
                    mma_f16(acc[mi][2 * njp],     AH[mi], BH[0], BH[1]);
                    mma_f16(acc[mi][2 * njp],     AH[mi], BL[0], BL[1]);
                    if (TP)
                        mma_f16(acc[mi][2 * njp], AL[mi], BH[0], BH[1]);
                    mma_f16(acc[mi][2 * njp + 1], AH[mi], BH[2], BH[3]);
                    mma_f16(acc[mi][2 * njp + 1], AH[mi], BL[2], BL[3]);
                    if (TP)
                        mma_f16(acc[mi][2 * njp + 1], AL[mi], BH[2], BH[3]);
                }
            }
        }
    }

    // Epilogue
#pragma unroll
    for (int mi = 0; mi < 4; mi++) {
#pragma unroll
        for (int nj = 0; nj < NJ; nj++) {
            int r0 = m0 + wm * 64 + mi * 16 + g;
            int cg = n0 + wn * (8 * NJ) + nj * 8 + 2 * tq;
            float* base;
            long long rs;
            __half* fb = 0;
            float fsc = 1.0f;
            if (zsplit) {
                int z = cg >> 7, o = cg & 127;
                base = C + (size_t)z * BSO + (size_t)r0 * 128 + o;
                rs = 128;
                if (Cf) fb = Cf + (size_t)z * BSO + (size_t)r0 * 128 + o;
                if (z < 8) fsc = QSCALE;     // pre-scale Q fp16 copies
            } else {
                base = C + (size_t)r0 * Ntot + cg;
                rs = Ntot;
            }
            float2 v0 = make_float2(acc[mi][nj][0], acc[mi][nj][1]);
            float2 v1 = make_float2(acc[mi][nj][2], acc[mi][nj][3]);
            *(float2*)base = v0;
            *(float2*)(base + 8 * rs) = v1;
            if (fb) {
                *(__half2*)fb = __floats2half2_rn(v0.x * fsc, v0.y * fsc);
                *(__half2*)(fb + 8 * rs) =
                    __floats2half2_rn(v1.x * fsc, v1.y * fsc);
            }
        }
    }
}

// ---------------------------------------------------------------------------
// Attention: fp16 HMMA filter (f16 accumulate, Q pre-scaled) + exact fp32
// re-check; epilogue writes ctx hi fp16 for the Wo GEMM.
// grid (S/64, H, B), 512 threads.
// ---------------------------------------------------------------------------
#define CAP 32
#define THRESH  40.0f
#define FMARGIN 60.0f
#define ATTN_SMEM ((3 * 64 * 68 + 64 * 68 + 64 + 64 * CAP + 64 + 64 * CAP) * 4)

__global__ __launch_bounds__(512) void attn_kernel()
{
    extern __shared__ __align__(16) uint32_t smu[];
    uint32_t* Qs   = smu;                       // 64 x 68 u32 (fp16 pairs)
    uint32_t* Ks   = Qs + 64 * 68;              // 2 x 64 x 68 u32
    float*    Sc   = (float*)(Ks + 2 * 64 * 68);// 64 x 68 approx scores
    float*    maxv = Sc + 64 * 68;              // 64
    float*    candS= maxv + 64;                 // 64 x CAP
    int*      cnt  = (int*)(candS + 64 * CAP);  // 64
    int*      candK= cnt + 64;                  // 64 x CAP

    const int t  = threadIdx.x;
    const int q0 = blockIdx.x * 64;
    const int h  = blockIdx.y;
    const int b  = blockIdx.z;

    const int r_ = t >> 3;
    const int c8 = (t & 7) << 3;

    {
        const uint4* Qgh = (const uint4*)(g_QKVh +
            ((long long)h * BSO + ((long long)b * S_ + q0) * O_));
        uint4 v0 = Qgh[r_ * 16 + (c8 >> 2)];
        uint4 v1 = Qgh[r_ * 16 + (c8 >> 2) + 1];
        *(uint4*)&Qs[r_ * 68 + c8]     = v0;
        *(uint4*)&Qs[r_ * 68 + c8 + 4] = v1;
    }
    if (t < 64) { maxv[t] = -1e30f; cnt[t] = 0; }

    const float* Kg = g_QKV + 8 * BSO + (long long)b * S_ * O_;
    const float* Vg = g_QKV + 9 * BSO + (long long)b * S_ * O_;
    const __half* Kgh = g_QKVh + 8 * BSO + (long long)b * S_ * O_;
    const float scale = QSCALE;

    const uint32_t ksb = smem_u32(Ks);
    auto fillK = [&](int kt, int buf) {
        uint32_t dst = ksb + (buf * 64 * 68 + r_ * 68 + c8) * 4;
        const __half* src = Kgh + ((long long)(kt * 64 + r_) * O_) + c8 * 2;
        cp16(dst, src);
        cp16(dst + 16, src + 8);
    };

    const int w = t >> 5, lane = t & 31;
    const int g = lane >> 2, tq = lane & 3;
    const int qb = (w >> 2) << 4, kb = (w & 3) << 4;

    fillK(0, 0);
    CP_COMMIT();

    for (int kt = 0; kt < S_ / 64; kt++) {
        const int cur = kt & 1;
        CP_WAIT0();
        __syncthreads();
        if (kt + 1 < S_ / 64) {
            fillK(kt + 1, cur ^ 1);
            CP_COMMIT();
        }

        {
            const uint32_t* Kb32 = Ks + cur * 64 * 68;
            uint32_t d0[2] = {0u, 0u};
            uint32_t d1[2] = {0u, 0u};
#pragma unroll
            for (int kc = 0; kc < 8; kc++) {
                const int co = kc * 8 + tq;
                uint32_t a0 = Qs[(qb + g) * 68 + co];
                uint32_t a1 = Qs[(qb + g + 8) * 68 + co];
                uint32_t a2 = Qs[(qb + g) * 68 + co + 4];
                uint32_t a3 = Qs[(qb + g + 8) * 68 + co + 4];
                uint32_t b0 = Kb32[(kb + g) * 68 + co];
                uint32_t b1 = Kb32[(kb + g) * 68 + co + 4];
                uint32_t b2 = Kb32[(kb + 8 + g) * 68 + co];
                uint32_t b3 = Kb32[(kb + 8 + g) * 68 + co + 4];
                mma_f16acc(d0, a0, a1, a2, a3, b0, b1);
                mma_f16acc(d1, a0, a1, a2, a3, b2, b3);
            }
            // unpack f16-acc results (Q pre-scaled, so values are final)
            float2 f;
            f = __half22float2(*(__half2*)&d0[0]);
            *(float2*)&Sc[(qb + g) * 68 + kb + 2 * tq] = f;
            f = __half22float2(*(__half2*)&d0[1]);
            *(float2*)&Sc[(qb + g + 8) * 68 + kb + 2 * tq] = f;
            f = __half22float2(*(__half2*)&d1[0]);
            *(float2*)&Sc[(qb + g) * 68 + kb + 8 + 2 * tq] = f;
            f = __half22float2(*(__half2*)&d1[1]);
            *(float2*)&Sc[(qb + g + 8) * 68 + kb + 8 + 2 * tq] = f;
        }
        __syncthreads();

        if (t < 64) {
            float mx = maxv[t];
            int c = cnt[t];
            float thr = mx - FMARGIN;
            const float4* sr = (const float4*)&Sc[t * 68];
            float* cS = &candS[t * CAP];
            int*   cK = &candK[t * CAP];
#pragma unroll 4
            for (int j4 = 0; j4 < 16; j4++) {
                float4 v = sr[j4];
                float m4 = fmaxf(fmaxf(v.x, v.y), fmaxf(v.z, v.w));
                if (m4 > thr) {
                    float ss[4] = {v.x, v.y, v.z, v.w};
#pragma unroll
                    for (int u = 0; u < 4; u++) {
                        float s = ss[u];
                        if (s > thr) {
                            if (s > mx) { mx = s; thr = mx - FMARGIN; }
                            if (c == CAP) {
                                int wj = 0;
                                for (int i = 0; i < CAP; i++)
                                    if (cS[i] > thr) {
                                        cS[wj] = cS[i]; cK[wj] = cK[i]; wj++;
                                    }
                                c = wj;
                            }
                            if (c < CAP) {
                                cS[c] = s; cK[c] = kt * 64 + j4 * 4 + u; c++;
                            } else {
                                int am = 0; float mv = cS[0];
                                for (int i = 1; i < CAP; i++)
                                    if (cS[i] < mv) { mv = cS[i]; am = i; }
                                if (s > mv) { cS[am] = s; cK[am] = kt * 64 + j4 * 4 + u; }
                            }
                        }
                    }
                }
            }
            maxv[t] = mx; cnt[t] = c;
        }
        __syncthreads();
    }

    // Final: exact fp32 re-check + softmax + V gather; write ctx hi fp16
    const float* Qg = g_QKV + (long long)h * BSO + ((long long)b * S_ + q0) * O_;
#pragma unroll
    for (int i = 0; i < 4; i++) {
        const int r = 4 * w + i;
        const int c = cnt[r];
        float* cS = &candS[r * CAP];
        int*   cK = &candK[r * CAP];
        const float4 qv = ((const float4*)(Qg + (long long)r * O_))[lane];

        for (int idx = 0; idx < c; idx++) {
            const float4 kv = ((const float4*)(Kg + (long long)cK[idx] * O_))[lane];
            float d = qv.x * kv.x + qv.y * kv.y + qv.z * kv.z + qv.w * kv.w;
#pragma unroll
            for (int o = 16; o; o >>= 1) d += __shfl_xor_sync(~0u, d, o);
            if (lane == 0) cS[idx] = d * scale;
        }
        __syncwarp();

        float mx = -1e30f;
        for (int idx = 0; idx < c; idx++) mx = fmaxf(mx, cS[idx]);

        float4 a = make_float4(0.f, 0.f, 0.f, 0.f);
        float l = 0.f;
        for (int idx = 0; idx < c; idx++) {
            float s = cS[idx];
            if (s < mx - THRESH) continue;
            float p = __expf(s - mx);
            const float4 v = ((const float4*)(Vg + (long long)cK[idx] * O_))[lane];
            l += p;
            a.x += p * v.x; a.y += p * v.y; a.z += p * v.z; a.w += p * v.w;
        }
        const float inv = 1.0f / l;
        float4 r4 = make_float4(a.x * inv, a.y * inv, a.z * inv, a.w * inv);

        // fp16 hi of ctx, written directly for the Wo GEMM (2-product)
        size_t ci = (((size_t)b * S_ + q0 + r) * H_ + h) * O_ + lane * 4;
        *(__half2*)(g_ch + ci)     = __floats2half2_rn(r4.x, r4.y);
        *(__half2*)(g_ch + ci + 2) = __floats2half2_rn(r4.z, r4.w);
    }
}

// ---------------------------------------------------------------------------
extern "C" void kernel_launch(void* const* d_in, const int* in_sizes, int n_in,
                              void* d_out, int out_size)
{
    const float* x  = (const float*)d_in[0];
    const float* Wq = (const float*)d_in[1];
    const float* Wk = (const float*)d_in[2];
    const float* Wv = (const float*)d_in[3];
    const float* Wo = (const float*)d_in[4];
    float* out = (float*)d_out;

    float *QKVp;
    __half *QKVh, *xh, *xl, *ch, *wT, *wo;
    cudaGetSymbolAddress((void**)&QKVp, g_QKV);
    cudaGetSymbolAddress((void**)&QKVh, g_QKVh);
    cudaGetSymbolAddress((void**)&xh, g_xh);
    cudaGetSymbolAddress((void**)&xl, g_xl);
    cudaGetSymbolAddress((void**)&ch, g_ch);
    cudaGetSymbolAddress((void**)&wT, g_wT);
    cudaGetSymbolAddress((void**)&wo, g_woT);

    const size_t wH  = (size_t)NMAT * O_ * E_;      // hi/lo half offset (QKV)
    const size_t woH = (size_t)E_ * H_ * O_;
    const size_t OE  = (size_t)O_ * E_;

    // smem per instantiation
    const int SM_QKV = 3 * (512 + 2 * 160) * HS * 4;  // <10,true>: 199680 B
    const int SM_WO  = 3 * (256 + 2 * 128) * HS * 4;  // <8,false>: 122880 B
    cudaFuncSetAttribute(hgemm3<10, true>,
                         cudaFuncAttributeMaxDynamicSharedMemorySize, SM_QKV);
    cudaFuncSetAttribute(hgemm3<8, false>,
                         cudaFuncAttributeMaxDynamicSharedMemorySize, SM_WO);
    cudaFuncSetAttribute(attn_kernel,
                         cudaFuncAttributeMaxDynamicSharedMemorySize, ATTN_SMEM);

    const int M = B_ * S_;  // 8192
    const int nX = M * E_;  // 8.4M

    // A-operand split: x -> fp16 hi/lo (once, reused by all 10 projections)
    split_h<<<nX / 4 / 256, 256>>>(x, xh, xl, nX);

    // Weight transpose + fp16 split into fused layout [z][N][K]
    transpose_split_h<<<dim3(O_ / 32, E_ / 32, H_), dim3(32, 8)>>>(
        Wq, wT, wT + wH, E_, O_, (long long)E_ * O_, (long long)OE);
    transpose_split_h<<<dim3(O_ / 32, E_ / 32, 1), dim3(32, 8)>>>(
        Wk, wT + 8 * OE, wT + wH + 8 * OE, E_, O_, 0, 0);
    transpose_split_h<<<dim3(O_ / 32, E_ / 32, 1), dim3(32, 8)>>>(
        Wv, wT + 9 * OE, wT + wH + 9 * OE, E_, O_, 0, 0);
    transpose_split_h<<<dim3(E_ / 32, (H_ * O_) / 32, 1), dim3(32, 8)>>>(
        Wo, wo, wo + woH, H_ * O_, E_, 0, 0);

    // Fused Q/K/V projections: Ntot = 1280, N-tile 160 -> 8 x 32 = 256 blocks
    hgemm3<10, true><<<dim3(NMAT * O_ / 160, M / 256), 256, SM_QKV>>>(
        xh, xl, wT, wT + wH, QKVp, QKVh, E_, NMAT * O_, 1);

    // Attention (fp16 f16-acc filter + exact re-check + gather; writes ch)
    attn_kernel<<<dim3(S_ / 64, H_, B_), 512, ATTN_SMEM>>>();

    // Output projection (2-product): (B*S, H*O) @ (H*O, E) -> d_out
    hgemm3<8, false><<<dim3(E_ / 128, M / 256), 256, SM_WO>>>(
        ch, ch, wo, wo + woH, out, (__half*)0, H_ * O_, E_, 0);
}

// round 17
// speedup vs baseline: 1.4056x; 1.0844x over previous
#include <cuda_runtime.h>
#include <cuda_fp16.h>
#include <cuda_bf16.h>
#include <cstdint>

// Problem constants
#define B_ 4
#define S_ 2048
#define E_ 1024
#define H_ 8
#define O_ 128

#define BSO ((size_t)B_ * S_ * O_)       // 1,048,576
#define NMAT (H_ + 2)                    // 8 Q heads + K + V

// Scratch (allocation-free: __device__ globals)
__device__ float g_QKV[NMAT * BSO];              // z<8: Q head z; 8: K; 9: V
__device__ __half g_QKVh[NMAT * BSO];            // fp16 copies (filter pass;
                                                 //  Q slices pre-scaled)
// fp16 hi/lo splits of GEMM A operands
__device__ __half g_xh[(size_t)B_ * S_ * E_];
__device__ __half g_xl[(size_t)B_ * S_ * E_];
__device__ __half g_ch[(size_t)B_ * S_ * H_ * O_];   // ctx hi (from attn)
// Transposed + fp16-split weights, layout [N][K]: QKV fused, Wo separate
__device__ __half g_wT[2][(size_t)NMAT * O_ * E_];
__device__ __half g_woT[2][(size_t)E_ * H_ * O_];

#define QSCALE 0.08838834764831845f     // 1/sqrt(128)

// ---------------------------------------------------------------------------
__device__ __forceinline__ void cp16(uint32_t dst, const void* src) {
    asm volatile("cp.async.ca.shared.global [%0], [%1], 16;"
                 :: "r"(dst), "l"(src));
}
#define CP_COMMIT() asm volatile("cp.async.commit_group;" ::: "memory")
#define CP_WAIT0()  asm volatile("cp.async.wait_group 0;" ::: "memory")
#define CP_WAIT1()  asm volatile("cp.async.wait_group 1;" ::: "memory")

__device__ __forceinline__ uint32_t smem_u32(const void* p) {
    uint32_t a;
    asm("{ .reg .u64 t; cvta.to.shared.u64 t, %1; cvt.u32.u64 %0, t; }"
        : "=r"(a) : "l"(p));
    return a;
}

// ldmatrix 4x(8x8) b16 fragments — baseline sm_75 PTX
__device__ __forceinline__ void ldm4(uint32_t* r, uint32_t addr) {
    asm volatile(
        "ldmatrix.sync.aligned.m8n8.x4.shared.b16 {%0,%1,%2,%3}, [%4];"
        : "=r"(r[0]), "=r"(r[1]), "=r"(r[2]), "=r"(r[3]) : "r"(addr));
}

// mma.sync m16n8k16 fp16 — D += A*B, fp32 accumulate (baseline sm_80 PTX)
__device__ __forceinline__ void mma_f16(float* d, const uint32_t a[4],
                                        uint32_t b0, uint32_t b1) {
    asm volatile(
        "mma.sync.aligned.m16n8k16.row.col.f32.f16.f16.f32 "
        "{%0,%1,%2,%3}, {%4,%5,%6,%7}, {%8,%9}, {%0,%1,%2,%3};"
        : "+f"(d[0]), "+f"(d[1]), "+f"(d[2]), "+f"(d[3])
        : "r"(a[0]), "r"(a[1]), "r"(a[2]), "r"(a[3]), "r"(b0), "r"(b1));
}

// mma.sync m16n8k16 fp16 — D += A*B, fp16 accumulate
__device__ __forceinline__ void mma_f16acc(uint32_t* d,
                                           uint32_t a0, uint32_t a1,
                                           uint32_t a2, uint32_t a3,
                                           uint32_t b0, uint32_t b1) {
    asm volatile(
        "mma.sync.aligned.m16n8k16.row.col.f16.f16.f16.f16 "
        "{%0,%1}, {%2,%3,%4,%5}, {%6,%7}, {%0,%1};"
        : "+r"(d[0]), "+r"(d[1])
        : "r"(a0), "r"(a1), "r"(a2), "r"(a3), "r"(b0), "r"(b1));
}

// ---------------------------------------------------------------------------
// fp32 -> fp16 hi/lo split, bulk (n % 4 == 0)
// ---------------------------------------------------------------------------
__global__ void split_h(const float* __restrict__ in,
                        __half* __restrict__ oh, __half* __restrict__ ol,
                        int n)
{
    int i = (blockIdx.x * blockDim.x + threadIdx.x) * 4;
    if (i < n) {
        float4 v = *(const float4*)(in + i);
        __half2 h0 = __floats2half2_rn(v.x, v.y);
        __half2 h1 = __floats2half2_rn(v.z, v.w);
        float2 f0 = __half22float2(h0);
        float2 f1 = __half22float2(h1);
        __half2 l0 = __floats2half2_rn(v.x - f0.x, v.y - f0.y);
        __half2 l1 = __floats2half2_rn(v.z - f1.x, v.w - f1.y);
        *(__half2*)(oh + i)     = h0;
        *(__half2*)(oh + i + 2) = h1;
        *(__half2*)(ol + i)     = l0;
        *(__half2*)(ol + i + 2) = l1;
    }
}

// ---------------------------------------------------------------------------
// Weight transpose + fp16 hi/lo split: in[K][N] (+z*sIn) -> hi/lo [N][K]
// grid (N/32, K/32, Z), block (32, 8)
// ---------------------------------------------------------------------------
__global__ void transpose_split_h(const float* __restrict__ in,
                                  __half* __restrict__ oh,
                                  __half* __restrict__ ol,
                                  int K, int N, long long sIn, long long sOut)
{
    __shared__ float t[32][33];
    const float* ip = in + (long long)blockIdx.z * sIn;
    __half* ph = oh + (long long)blockIdx.z * sOut;
    __half* pl = ol + (long long)blockIdx.z * sOut;
    const int n0 = blockIdx.x * 32, k0 = blockIdx.y * 32;
    const int tx = threadIdx.x, ty = threadIdx.y;
#pragma unroll
    for (int p = 0; p < 4; p++)
        t[ty + 8 * p][tx] = ip[(long long)(k0 + ty + 8 * p) * N + n0 + tx];
    __syncthreads();
#pragma unroll
    for (int p = 0; p < 4; p++) {
        float v = t[tx][ty + 8 * p];
        __half h = __float2half_rn(v);
        __half l = __float2half_rn(v - __half2float(h));
        long long o = (long long)(n0 + ty + 8 * p) * K + k0 + tx;
        ph[o] = h;
        pl[o] = l;
    }
}

// ---------------------------------------------------------------------------
// fp16 split GEMM v6 (templated N-tile + product count P):
// Block tile 256(M) x (16*NJ)(N) x 32(K), 256 threads, 8 warps (4m x 2n).
// P=3: Ah*Bh + Ah*Bl + Al*Bh (~22-bit exact)
// P=2: Ah*Bh + Ah*Bl (A treated as fp16-exact)
// P=1: Ah*Bh (plain fp16 GEMM, fp32 accumulate)
// zsplit=1: cols are [z][128] slices of stride BSO; fp16 copy Cf (Q pre-scaled)
// ---------------------------------------------------------------------------
#define HS 20                        // u32 stride per smem row (bank-clean)

template <int NJ, int P>
__global__ __launch_bounds__(256, 1) void hgemm3(
    const __half* __restrict__ Ah, const __half* __restrict__ Al,
    const __half* __restrict__ Bth, const __half* __restrict__ Btl,
    float* __restrict__ C, __half* __restrict__ Cf,
    int K, int Ntot, int zsplit)
{
    constexpr bool HAL = (P >= 3);               // A-lo present
    constexpr bool HBL = (P >= 2);               // B-lo present
    constexpr int NT    = 16 * NJ;               // block N-tile
    constexpr int NA    = HAL ? 512 : 256;       // A rows in smem
    constexpr int STA_L = 256 * HS;              // (used iff HAL)
    constexpr int STB_H = NA * HS;
    constexpr int STB_L = (NA + NT) * HS;        // (used iff HBL)
    constexpr int NB    = HBL ? 2 * NT : NT;     // B rows in smem
    constexpr int STAGE = (NA + NB) * HS;        // u32 per stage
    constexpr int VR    = NA + NB;               // virtual fill rows
    constexpr int NFJ   = (VR + 255) / 256;

    extern __shared__ __align__(16) uint32_t su[];
    const int tid = threadIdx.x, w = tid >> 5, lane = tid & 31;
    const int g = lane >> 2, tq = lane & 3;
    const int wm = w & 3, wn = w >> 2;
    const int m0 = blockIdx.y * 256, n0 = blockIdx.x * NT;
    const uint32_t sb = smem_u32(su);
    const int NK = K >> 5;

    // Fill precompute: VR virtual rows, thread handles rows tid + 256*j
    const __half* srcp[NFJ];
    uint32_t dsto[NFJ];
    bool valid[NFJ];
#pragma unroll
    for (int j = 0; j < NFJ; j++) {
        int vr = tid + (j << 8);
        valid[j] = vr < VR;
        int vc = valid[j] ? vr : 0;
        if (vc < 256)            { srcp[j] = Ah  + (size_t)(m0 + vc) * K;
                                   dsto[j] = vc * HS; }
        else if (HAL && vc < 512){ srcp[j] = Al  + (size_t)(m0 + vc - 256) * K;
                                   dsto[j] = STA_L + (vc - 256) * HS; }
        else if (vc < NA + NT)   { srcp[j] = Bth + (size_t)(n0 + vc - NA) * K;
                                   dsto[j] = STB_H + (vc - NA) * HS; }
        else                     { srcp[j] = Btl + (size_t)(n0 + vc - NA - NT) * K;
                                   dsto[j] = STB_L + (vc - NA - NT) * HS; }
    }
    auto fill = [&](int kt, int st) {
#pragma unroll
        for (int j = 0; j < NFJ; j++) {
            if (!valid[j]) continue;
            const __half* sp = srcp[j] + (kt << 5);
            uint32_t d = sb + (st * STAGE + dsto[j]) * 4;
            cp16(d, sp);           cp16(d + 16, sp + 8);
            cp16(d + 32, sp + 16); cp16(d + 48, sp + 24);
        }
    };

    // ldmatrix lane-relative offsets (u32 units)
    const uint32_t a_ro = (uint32_t)((wm * 64 + (lane & 15)) * HS +
                                     ((lane >> 4) << 2));
    const uint32_t b_ro = (uint32_t)((wn * (8 * NJ) + (lane & 7) +
                                      ((lane >> 4) << 3)) * HS +
                                     (((lane >> 3) & 1) << 2));

    float acc[4][NJ][4];
#pragma unroll
    for (int mi = 0; mi < 4; mi++)
#pragma unroll
        for (int nj = 0; nj < NJ; nj++)
#pragma unroll
            for (int q = 0; q < 4; q++) acc[mi][nj][q] = 0.f;

    // Prologue: stages 0, 1 in flight
    fill(0, 0);
    CP_COMMIT();
    if (NK > 1) { fill(1, 1); CP_COMMIT(); }

    for (int kt = 0; kt < NK; kt++) {
        if (kt + 1 < NK) { CP_WAIT1(); } else { CP_WAIT0(); }
        __syncthreads();                 // stage kt ready; stage (kt+2)%3 free
        if (kt + 2 < NK) {
            fill(kt + 2, (kt + 2) % 3);
            CP_COMMIT();
        }

        const uint32_t stb = sb + ((kt % 3) * STAGE) * 4;
#pragma unroll
        for (int ks = 0; ks < 2; ks++) {
            uint32_t AH[4][4], AL[4][4];
#pragma unroll
            for (int mi = 0; mi < 4; mi++) {
                uint32_t ao = stb + (a_ro + mi * 16 * HS + ks * 8) * 4;
                ldm4(AH[mi], ao);
                if (HAL) ldm4(AL[mi], ao + STA_L * 4);
            }
#pragma unroll
            for (int njp = 0; njp < NJ / 2; njp++) {
                uint32_t BH[4], BL[4];
                uint32_t bo = stb + (STB_H + b_ro + njp * 16 * HS + ks * 8) * 4;
                ldm4(BH, bo);
                if (HBL) ldm4(BL, bo + (STB_L - STB_H) * 4);
#pragma unroll
                for (int mi = 0; mi < 4; mi++) {
                    mma_f16(acc[mi][2 * njp],     AH[mi], BH[0], BH[1]);
                    if (HBL)
                        mma_f16(acc[mi][2 * njp], AH[mi], BL[0], BL[1]);
                    if (HAL)
                        mma_f16(acc[mi][2 * njp], AL[mi], BH[0], BH[1]);
                    mma_f16(acc[mi][2 * njp + 1], AH[mi], BH[2], BH[3]);
                    if (HBL)
                        mma_f16(acc[mi][2 * njp + 1], AH[mi], BL[2], BL[3]);
                    if (HAL)
                        mma_f16(acc[mi][2 * njp + 1], AL[mi], BH[2], BH[3]);
                }
            }
        }
    }

    // Epilogue
#pragma unroll
    for (int mi = 0; mi < 4; mi++) {
#pragma unroll
        for (int nj = 0; nj < NJ; nj++) {
            int r0 = m0 + wm * 64 + mi * 16 + g;
            int cg = n0 + wn * (8 * NJ) + nj * 8 + 2 * tq;
            float* base;
            long long rs;
            __half* fb = 0;
            float fsc = 1.0f;
            if (zsplit) {
                int z = cg >> 7, o = cg & 127;
                base = C + (size_t)z * BSO + (size_t)r0 * 128 + o;
                rs = 128;
                if (Cf) fb = Cf + (size_t)z * BSO + (size_t)r0 * 128 + o;
                if (z < 8) fsc = QSCALE;     // pre-scale Q fp16 copies
            } else {
                base = C + (size_t)r0 * Ntot + cg;
                rs = Ntot;
            }
            float2 v0 = make_float2(acc[mi][nj][0], acc[mi][nj][1]);
            float2 v1 = make_float2(acc[mi][nj][2], acc[mi][nj][3]);
            *(float2*)base = v0;
            *(float2*)(base + 8 * rs) = v1;
            if (fb) {
                *(__half2*)fb = __floats2half2_rn(v0.x * fsc, v0.y * fsc);
                *(__half2*)(fb + 8 * rs) =
                    __floats2half2_rn(v1.x * fsc, v1.y * fsc);
            }
        }
    }
}

// ---------------------------------------------------------------------------
// Attention: fp16 HMMA filter (f16 accumulate, Q pre-scaled) + exact fp32
// re-check; epilogue writes ctx hi fp16 for the Wo GEMM.
// grid (S/64, H, B), 512 threads.
// ---------------------------------------------------------------------------
#define CAP 32
#define THRESH  40.0f
#define FMARGIN 60.0f
#define ATTN_SMEM ((3 * 64 * 68 + 64 * 68 + 64 + 64 * CAP + 64 + 64 * CAP) * 4)

__global__ __launch_bounds__(512) void attn_kernel()
{
    extern __shared__ __align__(16) uint32_t smu[];
    uint32_t* Qs   = smu;                       // 64 x 68 u32 (fp16 pairs)
    uint32_t* Ks   = Qs + 64 * 68;              // 2 x 64 x 68 u32
    float*    Sc   = (float*)(Ks + 2 * 64 * 68);// 64 x 68 approx scores
    float*    maxv = Sc + 64 * 68;              // 64
    float*    candS= maxv + 64;                 // 64 x CAP
    int*      cnt  = (int*)(candS + 64 * CAP);  // 64
    int*      candK= cnt + 64;                  // 64 x CAP

    const int t  = threadIdx.x;
    const int q0 = blockIdx.x * 64;
    const int h  = blockIdx.y;
    const int b  = blockIdx.z;

    const int r_ = t >> 3;
    const int c8 = (t & 7) << 3;

    {
        const uint4* Qgh = (const uint4*)(g_QKVh +
            ((long long)h * BSO + ((long long)b * S_ + q0) * O_));
        uint4 v0 = Qgh[r_ * 16 + (c8 >> 2)];
        uint4 v1 = Qgh[r_ * 16 + (c8 >> 2) + 1];
        *(uint4*)&Qs[r_ * 68 + c8]     = v0;
        *(uint4*)&Qs[r_ * 68 + c8 + 4] = v1;
    }
    if (t < 64) { maxv[t] = -1e30f; cnt[t] = 0; }

    const float* Kg = g_QKV + 8 * BSO + (long long)b * S_ * O_;
    const float* Vg = g_QKV + 9 * BSO + (long long)b * S_ * O_;
    const __half* Kgh = g_QKVh + 8 * BSO + (long long)b * S_ * O_;
    const float scale = QSCALE;

    const uint32_t ksb = smem_u32(Ks);
    auto fillK = [&](int kt, int buf) {
        uint32_t dst = ksb + (buf * 64 * 68 + r_ * 68 + c8) * 4;
        const __half* src = Kgh + ((long long)(kt * 64 + r_) * O_) + c8 * 2;
        cp16(dst, src);
        cp16(dst + 16, src + 8);
    };

    const int w = t >> 5, lane = t & 31;
    const int g = lane >> 2, tq = lane & 3;
    const int qb = (w >> 2) << 4, kb = (w & 3) << 4;

    fillK(0, 0);
    CP_COMMIT();

    for (int kt = 0; kt < S_ / 64; kt++) {
        const int cur = kt & 1;
        CP_WAIT0();
        __syncthreads();
        if (kt + 1 < S_ / 64) {
            fillK(kt + 1, cur ^ 1);
            CP_COMMIT();
        }

        {
            const uint32_t* Kb32 = Ks + cur * 64 * 68;
            uint32_t d0[2] = {0u, 0u};
            uint32_t d1[2] = {0u, 0u};
#pragma unroll
            for (int kc = 0; kc < 8; kc++) {
                const int co = kc * 8 + tq;
                uint32_t a0 = Qs[(qb + g) * 68 + co];
                uint32_t a1 = Qs[(qb + g + 8) * 68 + co];
                uint32_t a2 = Qs[(qb + g) * 68 + co + 4];
                uint32_t a3 = Qs[(qb + g + 8) * 68 + co + 4];
                uint32_t b0 = Kb32[(kb + g) * 68 + co];
                uint32_t b1 = Kb32[(kb + g) * 68 + co + 4];
                uint32_t b2 = Kb32[(kb + 8 + g) * 68 + co];
                uint32_t b3 = Kb32[(kb + 8 + g) * 68 + co + 4];
                mma_f16acc(d0, a0, a1, a2, a3, b0, b1);
                mma_f16acc(d1, a0, a1, a2, a3, b2, b3);
            }
            // unpack f16-acc results (Q pre-scaled, so values are final)
            float2 f;
            f = __half22float2(*(__half2*)&d0[0]);
            *(float2*)&Sc[(qb + g) * 68 + kb + 2 * tq] = f;
            f = __half22float2(*(__half2*)&d0[1]);
            *(float2*)&Sc[(qb + g + 8) * 68 + kb + 2 * tq] = f;
            f = __half22float2(*(__half2*)&d1[0]);
            *(float2*)&Sc[(qb + g) * 68 + kb + 8 + 2 * tq] = f;
            f = __half22float2(*(__half2*)&d1[1]);
            *(float2*)&Sc[(qb + g + 8) * 68 + kb + 8 + 2 * tq] = f;
        }
        __syncthreads();

        if (t < 64) {
            float mx = maxv[t];
            int c = cnt[t];
            float thr = mx - FMARGIN;
            const float4* sr = (const float4*)&Sc[t * 68];
            float* cS = &candS[t * CAP];
            int*   cK = &candK[t * CAP];
#pragma unroll 4
            for (int j4 = 0; j4 < 16; j4++) {
                float4 v = sr[j4];
                float m4 = fmaxf(fmaxf(v.x, v.y), fmaxf(v.z, v.w));
                if (m4 > thr) {
                    float ss[4] = {v.x, v.y, v.z, v.w};
#pragma unroll
                    for (int u = 0; u < 4; u++) {
                        float s = ss[u];
                        if (s > thr) {
                            if (s > mx) { mx = s; thr = mx - FMARGIN; }
                            if (c == CAP) {
                                int wj = 0;
                                for (int i = 0; i < CAP; i++)
                                    if (cS[i] > thr) {
                                        cS[wj] = cS[i]; cK[wj] = cK[i]; wj++;
                                    }
                                c = wj;
                            }
                            if (c < CAP) {
                                cS[c] = s; cK[c] = kt * 64 + j4 * 4 + u; c++;
                            } else {
                                int am = 0; float mv = cS[0];
                                for (int i = 1; i < CAP; i++)
                                    if (cS[i] < mv) { mv = cS[i]; am = i; }
                                if (s > mv) { cS[am] = s; cK[am] = kt * 64 + j4 * 4 + u; }
                            }
                        }
                    }
                }
            }
            maxv[t] = mx; cnt[t] = c;
        }
        __syncthreads();
    }

    // Final: exact fp32 re-check + softmax + V gather; write ctx hi fp16
    const float* Qg = g_QKV + (long long)h * BSO + ((long long)b * S_ + q0) * O_;
#pragma unroll
    for (int i = 0; i < 4; i++) {
        const int r = 4 * w + i;
        const int c = cnt[r];
        float* cS = &candS[r * CAP];
        int*   cK = &candK[r * CAP];
        const float4 qv = ((const float4*)(Qg + (long long)r * O_))[lane];

        for (int idx = 0; idx < c; idx++) {
            const float4 kv = ((const float4*)(Kg + (long long)cK[idx] * O_))[lane];
            float d = qv.x * kv.x + qv.y * kv.y + qv.z * kv.z + qv.w * kv.w;
#pragma unroll
            for (int o = 16; o; o >>= 1) d += __shfl_xor_sync(~0u, d, o);
            if (lane == 0) cS[idx] = d * scale;
        }
        __syncwarp();

        float mx = -1e30f;
        for (int idx = 0; idx < c; idx++) mx = fmaxf(mx, cS[idx]);

        float4 a = make_float4(0.f, 0.f, 0.f, 0.f);
        float l = 0.f;
        for (int idx = 0; idx < c; idx++) {
            float s = cS[idx];
            if (s < mx - THRESH) continue;
            float p = __expf(s - mx);
            const float4 v = ((const float4*)(Vg + (long long)cK[idx] * O_))[lane];
            l += p;
            a.x += p * v.x; a.y += p * v.y; a.z += p * v.z; a.w += p * v.w;
        }
        const float inv = 1.0f / l;
        float4 r4 = make_float4(a.x * inv, a.y * inv, a.z * inv, a.w * inv);

        // fp16 hi of ctx, written directly for the Wo GEMM (1-product)
        size_t ci = (((size_t)b * S_ + q0 + r) * H_ + h) * O_ + lane * 4;
        *(__half2*)(g_ch + ci)     = __floats2half2_rn(r4.x, r4.y);
        *(__half2*)(g_ch + ci + 2) = __floats2half2_rn(r4.z, r4.w);
    }
}

// ---------------------------------------------------------------------------
extern "C" void kernel_launch(void* const* d_in, const int* in_sizes, int n_in,
                              void* d_out, int out_size)
{
    const float* x  = (const float*)d_in[0];
    const float* Wq = (const float*)d_in[1];
    const float* Wk = (const float*)d_in[2];
    const float* Wv = (const float*)d_in[3];
    const float* Wo = (const float*)d_in[4];
    float* out = (float*)d_out;

    float *QKVp;
    __half *QKVh, *xh, *xl, *ch, *wT, *wo;
    cudaGetSymbolAddress((void**)&QKVp, g_QKV);
    cudaGetSymbolAddress((void**)&QKVh, g_QKVh);
    cudaGetSymbolAddress((void**)&xh, g_xh);
    cudaGetSymbolAddress((void**)&xl, g_xl);
    cudaGetSymbolAddress((void**)&ch, g_ch);
    cudaGetSymbolAddress((void**)&wT, g_wT);
    cudaGetSymbolAddress((void**)&wo, g_woT);

    const size_t wH  = (size_t)NMAT * O_ * E_;      // hi/lo half offset (QKV)
    const size_t woH = (size_t)E_ * H_ * O_;
    const size_t OE  = (size_t)O_ * E_;

    // smem per instantiation
    const int SM_QKV = 3 * (512 + 2 * 160) * HS * 4;  // <10,3>: 199680 B
    const int SM_WO  = 3 * (256 + 128) * HS * 4;      // <8,1> :  92160 B
    cudaFuncSetAttribute(hgemm3<10, 3>,
                         cudaFuncAttributeMaxDynamicSharedMemorySize, SM_QKV);
    cudaFuncSetAttribute(hgemm3<8, 1>,
                         cudaFuncAttributeMaxDynamicSharedMemorySize, SM_WO);
    cudaFuncSetAttribute(attn_kernel,
                         cudaFuncAttributeMaxDynamicSharedMemorySize, ATTN_SMEM);

    const int M = B_ * S_;  // 8192
    const int nX = M * E_;  // 8.4M

    // A-operand split: x -> fp16 hi/lo (once, reused by all 10 projections)
    split_h<<<nX / 4 / 256, 256>>>(x, xh, xl, nX);

    // Weight transpose + fp16 split into fused layout [z][N][K]
    transpose_split_h<<<dim3(O_ / 32, E_ / 32, H_), dim3(32, 8)>>>(
        Wq, wT, wT + wH, E_, O_, (long long)E_ * O_, (long long)OE);
    transpose_split_h<<<dim3(O_ / 32, E_ / 32, 1), dim3(32, 8)>>>(
        Wk, wT + 8 * OE, wT + wH + 8 * OE, E_, O_, 0, 0);
    transpose_split_h<<<dim3(O_ / 32, E_ / 32, 1), dim3(32, 8)>>>(
        Wv, wT + 9 * OE, wT + wH + 9 * OE, E_, O_, 0, 0);
    transpose_split_h<<<dim3(E_ / 32, (H_ * O_) / 32, 1), dim3(32, 8)>>>(
        Wo, wo, wo + woH, H_ * O_, E_, 0, 0);

    // Fused Q/K/V projections: Ntot = 1280, N-tile 160 -> 8 x 32 = 256 blocks
    hgemm3<10, 3><<<dim3(NMAT * O_ / 160, M / 256), 256, SM_QKV>>>(
        xh, xl, wT, wT + wH, QKVp, QKVh, E_, NMAT * O_, 1);

    // Attention (fp16 f16-acc filter + exact re-check + gather; writes ch)
    attn_kernel<<<dim3(S_ / 64, H_, B_), 512, ATTN_SMEM>>>();

    // Output projection (1-product plain fp16): (B*S, H*O) @ (H*O, E) -> out
    hgemm3<8, 1><<<dim3(E_ / 128, M / 256), 256, SM_WO>>>(
        ch, ch, wo, wo, out, (__half*)0, H_ * O_, E_, 0);
}